// round 14
// baseline (speedup 1.0000x reference)
#include <cuda_runtime.h>
#include <cuda_fp16.h>
#include <stdint.h>
#include <math.h>

// Problem constants: N=100000, H=64, E=1600000, P=3
#define NMAX 100000
#define EMAX 1600000
#define HDIM 64
#define PNUM 3

typedef unsigned long long ull;

// ---------------- scratch (no allocation allowed -> device globals) -------
__device__ __align__(16) __half g_fts16[PNUM][NMAX * HDIM];   // 38.4 MB
__device__ __align__(16) __half g_embA[PNUM][NMAX * HDIM];    // 19.2 MB
__device__ __align__(16) __half g_embB[PNUM][NMAX * HDIM];    // 19.2 MB
__device__ float g_s[3][PNUM * HDIM];   // slot 0: pass1(A), 1: pass2(B), 2: pass3

// CSR scratch
__device__ int  g_deg[NMAX];
__device__ int  g_off[NMAX + 1];
__device__ int  g_cur[NMAX];
__device__ __align__(16) int2 g_edge[EMAX];   // .x = col | m1<<30 | m2<<31, .y = val bits

__device__ __forceinline__ float prelu_f(float x, float s) { return x > 0.f ? x : s * x; }

__device__ __forceinline__ uint32_t h2_bits(__half2 h)
{
    return *reinterpret_cast<uint32_t*>(&h);
}

// ---- packed f32x2 helpers ----
__device__ __forceinline__ ull packf2(float lo, float hi)
{
    ull r;
    asm("mov.b64 %0, {%1,%2};" : "=l"(r) : "f"(lo), "f"(hi));
    return r;
}
__device__ __forceinline__ void unpackf2(ull v, float& lo, float& hi)
{
    asm("mov.b64 {%0,%1}, %2;" : "=f"(lo), "=f"(hi) : "l"(v));
}
// d += a*b (elementwise on packed f32x2)
__device__ __forceinline__ void ffma2(ull& d, ull a, ull b)
{
    asm("fma.rn.f32x2 %0, %1, %2, %3;" : "=l"(d) : "l"(a), "l"(b), "l"(d));
}
// convert half2 pair (uint2) into two packed f32x2
__device__ __forceinline__ void h4_to_f2x2(uint2 u, ull& lo, ull& hi)
{
    float2 f01 = __half22float2(*(const __half2*)&u.x);
    float2 f23 = __half22float2(*(const __half2*)&u.y);
    lo = packf2(f01.x, f01.y);
    hi = packf2(f23.x, f23.y);
}

// m16n8k16 row.col HMMA, fp16 inputs, fp32 accumulate
__device__ __forceinline__ void mma_16816(float* c, const uint32_t* a, const uint32_t* b)
{
    asm volatile("mma.sync.aligned.m16n8k16.row.col.f32.f16.f16.f32 "
                 "{%0,%1,%2,%3}, {%4,%5,%6,%7}, {%8,%9}, {%0,%1,%2,%3};"
                 : "+f"(c[0]), "+f"(c[1]), "+f"(c[2]), "+f"(c[3])
                 : "r"(a[0]), "r"(a[1]), "r"(a[2]), "r"(a[3]), "r"(b[0]), "r"(b[1]));
}

#define APAD 72   // padded half-stride: conflict-free 4B fragment loads

__device__ __forceinline__ float4 gath_mul(uint2 u, float v)
{
    float2 f01 = __half22float2(*(const __half2*)&u.x);
    float2 f23 = __half22float2(*(const __half2*)&u.y);
    return make_float4(f01.x * v, f01.y * v, f23.x * v, f23.y * v);
}
__device__ __forceinline__ uint2 pack_half4(float4 a)
{
    __half2 h0 = __floats2half2_rn(a.x, a.y);
    __half2 h1 = __floats2half2_rn(a.z, a.w);
    return make_uint2(h2_bits(h0), h2_bits(h1));
}
__device__ __forceinline__ uint2 pack_half4_u(ull lo, ull hi)
{
    float a, b, c, d;
    unpackf2(lo, a, b);
    unpackf2(hi, c, d);
    __half2 h0 = __floats2half2_rn(a, b);
    __half2 h1 = __floats2half2_rn(c, d);
    return make_uint2(h2_bits(h0), h2_bits(h1));
}

// per-block beta = softmax_p( (colsum_p . att) / n ) from g_s[slot]
__device__ __forceinline__ void block_beta(float* sbeta, int slot,
                                           const float* __restrict__ att, int n)
{
    int t = threadIdx.x;
    int w = t >> 5, l = t & 31;
    if (w < PNUM) {
        float v = g_s[slot][w * 64 + l] * __ldg(att + l)
                + g_s[slot][w * 64 + 32 + l] * __ldg(att + 32 + l);
#pragma unroll
        for (int o = 16; o; o >>= 1) v += __shfl_down_sync(0xffffffffu, v, o);
        if (l == 0) sbeta[w] = v / (float)n;
    }
    __syncthreads();
    if (t == 0) {
        float m = fmaxf(sbeta[0], fmaxf(sbeta[1], sbeta[2]));
        float e0 = expf(sbeta[0] - m), e1 = expf(sbeta[1] - m), e2 = expf(sbeta[2] - m);
        float inv = 1.f / (e0 + e1 + e2);
        sbeta[0] = e0 * inv; sbeta[1] = e1 * inv; sbeta[2] = e2 * inv;
    }
    __syncthreads();
}

// ===========================================================================
// CSR build (hist & scatter vectorized: 4 edges per thread)
// ===========================================================================
__global__ void csr_zero(int n)
{
    int i = blockIdx.x * blockDim.x + threadIdx.x;
    if (i < n) g_deg[i] = 0;
}
__global__ void csr_hist(const int* __restrict__ row, int e)
{
    int i = (blockIdx.x * blockDim.x + threadIdx.x) * 4;
    if (i + 4 <= e) {
        int4 r = __ldg((const int4*)(row + i));
        atomicAdd(&g_deg[r.x], 1);
        atomicAdd(&g_deg[r.y], 1);
        atomicAdd(&g_deg[r.z], 1);
        atomicAdd(&g_deg[r.w], 1);
    } else {
        for (; i < e; i++) atomicAdd(&g_deg[__ldg(row + i)], 1);
    }
}
__global__ void csr_scan(int n)
{
    __shared__ int part[1024];
    int tid = threadIdx.x;
    int chunk = (n + 1023) >> 10;
    int beg = tid * chunk;
    int end = min(beg + chunk, n);
    int s = 0;
    for (int i = beg; i < end; i++) s += g_deg[i];
    part[tid] = s;
    __syncthreads();
    for (int o = 1; o < 1024; o <<= 1) {
        int t2 = (tid >= o) ? part[tid - o] : 0;
        __syncthreads();
        part[tid] += t2;
        __syncthreads();
    }
    int run = part[tid] - s;
    for (int i = beg; i < end; i++) {
        g_off[i] = run; g_cur[i] = run;
        run += g_deg[i];
    }
    if (tid == 1023) g_off[n] = part[1023];
}
__global__ void csr_scatter(const int* __restrict__ row, const int* __restrict__ col,
                            const float* __restrict__ vals,
                            const int* __restrict__ mask1, const int* __restrict__ mask2,
                            int e)
{
    if (blockIdx.x == 0 && threadIdx.x < PNUM * HDIM) {
        g_s[0][threadIdx.x] = 0.f;
        g_s[1][threadIdx.x] = 0.f;
        g_s[2][threadIdx.x] = 0.f;
    }
    int i = (blockIdx.x * blockDim.x + threadIdx.x) * 4;
    if (i + 4 <= e) {
        int4 r = __ldg((const int4*)(row + i));
        int4 c = __ldg((const int4*)(col + i));
        float4 v = __ldg((const float4*)(vals + i));
        int cs[4] = {c.x, c.y, c.z, c.w};
        int rs[4] = {r.x, r.y, r.z, r.w};
        float vs[4] = {v.x, v.y, v.z, v.w};
#pragma unroll
        for (int j = 0; j < 4; j++) {
            int fl = cs[j] | (__ldg(mask1 + cs[j]) ? (1 << 30) : 0)
                           | (__ldg(mask2 + cs[j]) ? (1u << 31) : 0);
            int pos = atomicAdd(&g_cur[rs[j]], 1);
            g_edge[pos] = make_int2(fl, __float_as_int(vs[j]));
        }
    } else {
        for (; i < e; i++) {
            int rr = __ldg(row + i), cc = __ldg(col + i);
            float vv = __ldg(vals + i);
            int fl = cc | (__ldg(mask1 + cc) ? (1 << 30) : 0)
                        | (__ldg(mask2 + cc) ? (1u << 31) : 0);
            int pos = atomicAdd(&g_cur[rr], 1);
            g_edge[pos] = make_int2(fl, __float_as_int(vv));
        }
    }
}

// ===========================================================================
// GCN GEMM via HMMA (fp32 input): loop p per 128-row tile
// ===========================================================================
__global__ __launch_bounds__(128) void gemm_gcn_mma(
    const float* __restrict__ X, const float* __restrict__ Wall, int n)
{
    __shared__ __half smA[128 * APAD];
    __shared__ __half smB[64 * APAD];

    int t = threadIdx.x, wid = t >> 5, lane = t & 31;
    int g = lane >> 2, q = lane & 3;
    int rowBase = blockIdx.x * 128;

#pragma unroll
    for (int i = 0; i < 16; i++) {
        int idx = t + i * 128;
        int r = idx >> 4, k4 = idx & 15;
        int gr = rowBase + r;
        float4 v = make_float4(0.f, 0.f, 0.f, 0.f);
        if (gr < n) v = __ldg(((const float4*)X) + gr * 16 + k4);
        __half* dst = &smA[r * APAD + k4 * 4];
        *(__half2*)(dst)     = __floats2half2_rn(v.x, v.y);
        *(__half2*)(dst + 2) = __floats2half2_rn(v.z, v.w);
    }

    for (int p = 0; p < PNUM; p++) {
        __syncthreads();
#pragma unroll
        for (int i = 0; i < 8; i++) {
            int idx = t + i * 128;
            int r = idx >> 4, k4 = idx & 15;
            float4 v = __ldg(((const float4*)(Wall + p * 4096)) + r * 16 + k4);
            __half* dst = &smB[r * APAD + k4 * 4];
            *(__half2*)(dst)     = __floats2half2_rn(v.x, v.y);
            *(__half2*)(dst + 2) = __floats2half2_rn(v.z, v.w);
        }
        __syncthreads();

        float acc[2][8][4];
#pragma unroll
        for (int mt = 0; mt < 2; mt++)
#pragma unroll
            for (int nt = 0; nt < 8; nt++)
#pragma unroll
                for (int c = 0; c < 4; c++) acc[mt][nt][c] = 0.f;

#pragma unroll
        for (int ks = 0; ks < 4; ks++) {
            uint32_t afr[2][4];
#pragma unroll
            for (int mt = 0; mt < 2; mt++) {
                int r0 = wid * 32 + mt * 16 + g;
                int kb = ks * 16 + q * 2;
                afr[mt][0] = *(const uint32_t*)&smA[r0 * APAD + kb];
                afr[mt][1] = *(const uint32_t*)&smA[(r0 + 8) * APAD + kb];
                afr[mt][2] = *(const uint32_t*)&smA[r0 * APAD + kb + 8];
                afr[mt][3] = *(const uint32_t*)&smA[(r0 + 8) * APAD + kb + 8];
            }
#pragma unroll
            for (int nt = 0; nt < 8; nt++) {
                int cb = (nt * 8 + g) * APAD + ks * 16 + q * 2;
                uint32_t bfr[2];
                bfr[0] = *(const uint32_t*)&smB[cb];
                bfr[1] = *(const uint32_t*)&smB[cb + 8];
                mma_16816(acc[0][nt], afr[0], bfr);
                mma_16816(acc[1][nt], afr[1], bfr);
            }
        }

        __half* F = g_fts16[p];
#pragma unroll
        for (int mt = 0; mt < 2; mt++) {
            int r0 = rowBase + wid * 32 + mt * 16 + g;
#pragma unroll
            for (int nt = 0; nt < 8; nt++) {
                int col = nt * 8 + q * 2;
                if (r0 < n)
                    *(__half2*)(F + (size_t)r0 * 64 + col) =
                        __floats2half2_rn(acc[mt][nt][0], acc[mt][nt][1]);
                if (r0 + 8 < n)
                    *(__half2*)(F + (size_t)(r0 + 8) * 64 + col) =
                        __floats2half2_rn(acc[mt][nt][2], acc[mt][nt][3]);
            }
        }
    }
}

// ===========================================================================
// Pass-3 GCN GEMM with FUSED combine: z = sum_p beta0_p*prelu(embA_p) built
// in-register per tile, then fts16[p] = z @ W[p]^T.
// ===========================================================================
__global__ __launch_bounds__(128) void gemm_fused_z(
    const float* __restrict__ Wall, const float* __restrict__ a,
    const float* __restrict__ att, int n)
{
    __shared__ __half smA[128 * APAD];
    __shared__ __half smB[64 * APAD];
    __shared__ float sbeta[PNUM];

    int t = threadIdx.x, wid = t >> 5, lane = t & 31;
    int g = lane >> 2, q = lane & 3;
    int rowBase = blockIdx.x * 128;

    block_beta(sbeta, 0, att, n);
    float b0 = sbeta[0], b1 = sbeta[1], b2 = sbeta[2];
    float s0 = __ldg(a), s1 = __ldg(a + 1), s2 = __ldg(a + 2);

#pragma unroll
    for (int i = 0; i < 16; i++) {
        int idx = t + i * 128;
        int r = idx >> 4, k4 = idx & 15;
        int gr = rowBase + r;
        float4 z = make_float4(0.f, 0.f, 0.f, 0.f);
        if (gr < n) {
            float4 e0 = gath_mul(*((const uint2*)(g_embA[0] + (size_t)gr * 64 + k4 * 4)), 1.f);
            float4 e1 = gath_mul(*((const uint2*)(g_embA[1] + (size_t)gr * 64 + k4 * 4)), 1.f);
            float4 e2 = gath_mul(*((const uint2*)(g_embA[2] + (size_t)gr * 64 + k4 * 4)), 1.f);
            z.x = b0 * prelu_f(e0.x, s0) + b1 * prelu_f(e1.x, s1) + b2 * prelu_f(e2.x, s2);
            z.y = b0 * prelu_f(e0.y, s0) + b1 * prelu_f(e1.y, s1) + b2 * prelu_f(e2.y, s2);
            z.z = b0 * prelu_f(e0.z, s0) + b1 * prelu_f(e1.z, s1) + b2 * prelu_f(e2.z, s2);
            z.w = b0 * prelu_f(e0.w, s0) + b1 * prelu_f(e1.w, s1) + b2 * prelu_f(e2.w, s2);
        }
        __half* dst = &smA[r * APAD + k4 * 4];
        *(__half2*)(dst)     = __floats2half2_rn(z.x, z.y);
        *(__half2*)(dst + 2) = __floats2half2_rn(z.z, z.w);
    }

    for (int p = 0; p < PNUM; p++) {
        __syncthreads();
#pragma unroll
        for (int i = 0; i < 8; i++) {
            int idx = t + i * 128;
            int r = idx >> 4, k4 = idx & 15;
            float4 v = __ldg(((const float4*)(Wall + p * 4096)) + r * 16 + k4);
            __half* dst = &smB[r * APAD + k4 * 4];
            *(__half2*)(dst)     = __floats2half2_rn(v.x, v.y);
            *(__half2*)(dst + 2) = __floats2half2_rn(v.z, v.w);
        }
        __syncthreads();

        float acc[2][8][4];
#pragma unroll
        for (int mt = 0; mt < 2; mt++)
#pragma unroll
            for (int nt = 0; nt < 8; nt++)
#pragma unroll
                for (int c = 0; c < 4; c++) acc[mt][nt][c] = 0.f;

#pragma unroll
        for (int ks = 0; ks < 4; ks++) {
            uint32_t afr[2][4];
#pragma unroll
            for (int mt = 0; mt < 2; mt++) {
                int r0 = wid * 32 + mt * 16 + g;
                int kb = ks * 16 + q * 2;
                afr[mt][0] = *(const uint32_t*)&smA[r0 * APAD + kb];
                afr[mt][1] = *(const uint32_t*)&smA[(r0 + 8) * APAD + kb];
                afr[mt][2] = *(const uint32_t*)&smA[r0 * APAD + kb + 8];
                afr[mt][3] = *(const uint32_t*)&smA[(r0 + 8) * APAD + kb + 8];
            }
#pragma unroll
            for (int nt = 0; nt < 8; nt++) {
                int cb = (nt * 8 + g) * APAD + ks * 16 + q * 2;
                uint32_t bfr[2];
                bfr[0] = *(const uint32_t*)&smB[cb];
                bfr[1] = *(const uint32_t*)&smB[cb + 8];
                mma_16816(acc[0][nt], afr[0], bfr);
                mma_16816(acc[1][nt], afr[1], bfr);
            }
        }

        __half* F = g_fts16[p];
#pragma unroll
        for (int mt = 0; mt < 2; mt++) {
            int r0 = rowBase + wid * 32 + mt * 16 + g;
#pragma unroll
            for (int nt = 0; nt < 8; nt++) {
                int col = nt * 8 + q * 2;
                if (r0 < n)
                    *(__half2*)(F + (size_t)r0 * 64 + col) =
                        __floats2half2_rn(acc[mt][nt][0], acc[mt][nt][1]);
                if (r0 + 8 < n)
                    *(__half2*)(F + (size_t)(r0 + 8) * 64 + col) =
                        __floats2half2_rn(acc[mt][nt][2], acc[mt][nt][3]);
            }
        }
    }
}

// ===========================================================================
// Attention GEMM via HMMA: grid = (tiles, p). slot selects g_s; useB embB/embA
// ===========================================================================
__global__ __launch_bounds__(128) void att_gemm_mma(
    int slot, int useB, const float* __restrict__ a,
    const float* __restrict__ fcw, const float* __restrict__ fcb, int n)
{
    __shared__ __half smA[128 * APAD];
    __shared__ __half smB[64 * APAD];
    __shared__ float ssum[64];

    int t = threadIdx.x, wid = t >> 5, lane = t & 31;
    int g = lane >> 2, q = lane & 3;
    int rowBase = blockIdx.x * 128;
    int p = blockIdx.y;
    float sa = __ldg(a + p);
    const __half* E = useB ? g_embB[p] : g_embA[p];

    if (t < 64) ssum[t] = 0.f;

#pragma unroll
    for (int i = 0; i < 16; i++) {
        int idx = t + i * 128;
        int r = idx >> 4, k4 = idx & 15;
        int gr = rowBase + r;
        float4 v = make_float4(0.f, 0.f, 0.f, 0.f);
        if (gr < n) {
            uint2 u = *((const uint2*)(E + (size_t)gr * 64 + k4 * 4));
            float2 f01 = __half22float2(*(__half2*)&u.x);
            float2 f23 = __half22float2(*(__half2*)&u.y);
            v.x = prelu_f(f01.x, sa); v.y = prelu_f(f01.y, sa);
            v.z = prelu_f(f23.x, sa); v.w = prelu_f(f23.y, sa);
        }
        __half* dst = &smA[r * APAD + k4 * 4];
        *(__half2*)(dst)     = __floats2half2_rn(v.x, v.y);
        *(__half2*)(dst + 2) = __floats2half2_rn(v.z, v.w);
    }
#pragma unroll
    for (int i = 0; i < 8; i++) {
        int idx = t + i * 128;
        int r = idx >> 4, k4 = idx & 15;
        float4 v = __ldg(((const float4*)fcw) + r * 16 + k4);
        __half* dst = &smB[r * APAD + k4 * 4];
        *(__half2*)(dst)     = __floats2half2_rn(v.x, v.y);
        *(__half2*)(dst + 2) = __floats2half2_rn(v.z, v.w);
    }
    __syncthreads();

    float acc[2][8][4];
#pragma unroll
    for (int mt = 0; mt < 2; mt++)
#pragma unroll
        for (int nt = 0; nt < 8; nt++)
#pragma unroll
            for (int c = 0; c < 4; c++) acc[mt][nt][c] = 0.f;

#pragma unroll
    for (int ks = 0; ks < 4; ks++) {
        uint32_t afr[2][4];
#pragma unroll
        for (int mt = 0; mt < 2; mt++) {
            int r0 = wid * 32 + mt * 16 + g;
            int kb = ks * 16 + q * 2;
            afr[mt][0] = *(const uint32_t*)&smA[r0 * APAD + kb];
            afr[mt][1] = *(const uint32_t*)&smA[(r0 + 8) * APAD + kb];
            afr[mt][2] = *(const uint32_t*)&smA[r0 * APAD + kb + 8];
            afr[mt][3] = *(const uint32_t*)&smA[(r0 + 8) * APAD + kb + 8];
        }
#pragma unroll
        for (int nt = 0; nt < 8; nt++) {
            int cb = (nt * 8 + g) * APAD + ks * 16 + q * 2;
            uint32_t bfr[2];
            bfr[0] = *(const uint32_t*)&smB[cb];
            bfr[1] = *(const uint32_t*)&smB[cb + 8];
            mma_16816(acc[0][nt], afr[0], bfr);
            mma_16816(acc[1][nt], afr[1], bfr);
        }
    }

    float colsum[16];
#pragma unroll
    for (int i = 0; i < 16; i++) colsum[i] = 0.f;
#pragma unroll
    for (int mt = 0; mt < 2; mt++) {
        int r0 = rowBase + wid * 32 + mt * 16 + g;
#pragma unroll
        for (int nt = 0; nt < 8; nt++) {
            int col = nt * 8 + q * 2;
            float fb0 = __ldg(fcb + col), fb1 = __ldg(fcb + col + 1);
            if (r0 < n) {
                colsum[nt * 2]     += tanhf(acc[mt][nt][0] + fb0);
                colsum[nt * 2 + 1] += tanhf(acc[mt][nt][1] + fb1);
            }
            if (r0 + 8 < n) {
                colsum[nt * 2]     += tanhf(acc[mt][nt][2] + fb0);
                colsum[nt * 2 + 1] += tanhf(acc[mt][nt][3] + fb1);
            }
        }
    }
#pragma unroll
    for (int o = 4; o < 32; o <<= 1) {
#pragma unroll
        for (int i = 0; i < 16; i++)
            colsum[i] += __shfl_xor_sync(0xffffffffu, colsum[i], o);
    }
    if (lane < 4) {
#pragma unroll
        for (int nt = 0; nt < 8; nt++) {
            atomicAdd(&ssum[nt * 8 + q * 2], colsum[nt * 2]);
            atomicAdd(&ssum[nt * 8 + q * 2 + 1], colsum[nt * 2 + 1]);
        }
    }
    __syncthreads();
    if (t < 64) atomicAdd(&g_s[slot][p * 64 + t], ssum[t]);
}

// ===========================================================================
// CSR SpMM: 16 lanes/row (R9 shape), packed f32x2 FMA inner loop.
// ===========================================================================
__global__ __launch_bounds__(256) void spmm_dual_all(const float* __restrict__ b, int n)
{
    int rr = blockIdx.x * 16 + (threadIdx.x >> 4);
    int l = threadIdx.x & 15;
    if (rr >= n) return;
    int beg = g_off[rr], end = g_off[rr + 1];

    ull aA[PNUM][2], aB[PNUM][2];
#pragma unroll
    for (int p = 0; p < PNUM; p++) {
        float4 bias = __ldg(((const float4*)(b + p * HDIM)) + l);
        aA[p][0] = packf2(bias.x, bias.y);
        aA[p][1] = packf2(bias.z, bias.w);
        aB[p][0] = aA[p][0];
        aB[p][1] = aA[p][1];
    }

    int i = beg;
#pragma unroll 1
    for (; i + 4 <= end; i += 4) {
        int2 ed[4];
#pragma unroll
        for (int j = 0; j < 4; j++) ed[j] = __ldg(g_edge + i + j);
        uint2 u[4][PNUM];
#pragma unroll
        for (int j = 0; j < 4; j++) {
            int c = ed[j].x & 0xFFFFFF;
#pragma unroll
            for (int p = 0; p < PNUM; p++)
                u[j][p] = __ldg(((const uint2*)g_fts16[p]) + c * 16 + l);
        }
#pragma unroll
        for (int j = 0; j < 4; j++) {
            float v = __int_as_float(ed[j].y);
            float vA = (ed[j].x & (1 << 30)) ? 0.f : v;
            ull vv = packf2(v, v);
            ull vvA = packf2(vA, vA);
#pragma unroll
            for (int p = 0; p < PNUM; p++) {
                ull flo, fhi;
                h4_to_f2x2(u[j][p], flo, fhi);
                ffma2(aB[p][0], flo, vv);
                ffma2(aB[p][1], fhi, vv);
                ffma2(aA[p][0], flo, vvA);
                ffma2(aA[p][1], fhi, vvA);
            }
        }
    }
#pragma unroll 1
    for (; i < end; i++) {
        int2 ed = __ldg(g_edge + i);
        int c = ed.x & 0xFFFFFF;
        float v = __int_as_float(ed.y);
        float vA = (ed.x & (1 << 30)) ? 0.f : v;
        ull vv = packf2(v, v);
        ull vvA = packf2(vA, vA);
#pragma unroll
        for (int p = 0; p < PNUM; p++) {
            uint2 u = __ldg(((const uint2*)g_fts16[p]) + c * 16 + l);
            ull flo, fhi;
            h4_to_f2x2(u, flo, fhi);
            ffma2(aB[p][0], flo, vv);
            ffma2(aB[p][1], fhi, vv);
            ffma2(aA[p][0], flo, vvA);
            ffma2(aA[p][1], fhi, vvA);
        }
    }
#pragma unroll
    for (int p = 0; p < PNUM; p++) {
        ((uint2*)g_embA[p])[rr * 16 + l] = pack_half4_u(aA[p][0], aA[p][1]);
        ((uint2*)g_embB[p])[rr * 16 + l] = pack_half4_u(aB[p][0], aB[p][1]);
    }
}

// Pass-3 SpMM: skip gathers for mask2 edges; packed f32x2 FMA.
__global__ __launch_bounds__(256) void spmm_mask_all(const float* __restrict__ b, int n)
{
    int rr = blockIdx.x * 16 + (threadIdx.x >> 4);
    int l = threadIdx.x & 15;
    if (rr >= n) return;
    int beg = g_off[rr], end = g_off[rr + 1];

    ull aA[PNUM][2];
#pragma unroll
    for (int p = 0; p < PNUM; p++) {
        float4 bias = __ldg(((const float4*)(b + p * HDIM)) + l);
        aA[p][0] = packf2(bias.x, bias.y);
        aA[p][1] = packf2(bias.z, bias.w);
    }

    int i = beg;
#pragma unroll 1
    for (; i + 4 <= end; i += 4) {
        int2 ed[4];
#pragma unroll
        for (int j = 0; j < 4; j++) ed[j] = __ldg(g_edge + i + j);
#pragma unroll
        for (int j = 0; j < 4; j++) {
            if (ed[j].x & (1u << 31)) continue;
            int c = ed[j].x & 0xFFFFFF;
            float v = __int_as_float(ed[j].y);
            ull vv = packf2(v, v);
#pragma unroll
            for (int p = 0; p < PNUM; p++) {
                uint2 u = __ldg(((const uint2*)g_fts16[p]) + c * 16 + l);
                ull flo, fhi;
                h4_to_f2x2(u, flo, fhi);
                ffma2(aA[p][0], flo, vv);
                ffma2(aA[p][1], fhi, vv);
            }
        }
    }
#pragma unroll 1
    for (; i < end; i++) {
        int2 ed = __ldg(g_edge + i);
        if (ed.x & (1u << 31)) continue;
        int c = ed.x & 0xFFFFFF;
        float v = __int_as_float(ed.y);
        ull vv = packf2(v, v);
#pragma unroll
        for (int p = 0; p < PNUM; p++) {
            uint2 u = __ldg(((const uint2*)g_fts16[p]) + c * 16 + l);
            ull flo, fhi;
            h4_to_f2x2(u, flo, fhi);
            ffma2(aA[p][0], flo, vv);
            ffma2(aA[p][1], fhi, vv);
        }
    }
#pragma unroll
    for (int p = 0; p < PNUM; p++)
        ((uint2*)g_embA[p])[rr * 16 + l] = pack_half4_u(aA[p][0], aA[p][1]);
}

// ===========================================================================
// combine: inline softmax(beta) from g_s[slot], then weighted prelu-combine
// ===========================================================================
__global__ void combine_k(int slot, int useB, const float* __restrict__ a,
                          const float* __restrict__ att, float* __restrict__ out, int n)
{
    __shared__ float sbeta[PNUM];
    block_beta(sbeta, slot, att, n);

    int idx = blockIdx.x * blockDim.x + threadIdx.x;
    if (idx >= n * 16) return;
    float b0 = sbeta[0], b1 = sbeta[1], b2 = sbeta[2];
    float s0 = __ldg(a), s1 = __ldg(a + 1), s2 = __ldg(a + 2);
    const uint2* E0 = (const uint2*)(useB ? g_embB[0] : g_embA[0]);
    const uint2* E1 = (const uint2*)(useB ? g_embB[1] : g_embA[1]);
    const uint2* E2 = (const uint2*)(useB ? g_embB[2] : g_embA[2]);
    float4 e0 = gath_mul(E0[idx], 1.f);
    float4 e1 = gath_mul(E1[idx], 1.f);
    float4 e2 = gath_mul(E2[idx], 1.f);
    float4 o;
    o.x = b0 * prelu_f(e0.x, s0) + b1 * prelu_f(e1.x, s1) + b2 * prelu_f(e2.x, s2);
    o.y = b0 * prelu_f(e0.y, s0) + b1 * prelu_f(e1.y, s1) + b2 * prelu_f(e2.y, s2);
    o.z = b0 * prelu_f(e0.z, s0) + b1 * prelu_f(e1.z, s1) + b2 * prelu_f(e2.z, s2);
    o.w = b0 * prelu_f(e0.w, s0) + b1 * prelu_f(e1.w, s1) + b2 * prelu_f(e2.w, s2);
    ((float4*)out)[idx] = o;
}

// ===========================================================================
extern "C" void kernel_launch(void* const* d_in, const int* in_sizes, int n_in,
                              void* d_out, int out_size)
{
    const float* h     = (const float*)d_in[0];
    const float* W     = (const float*)d_in[1];
    const float* b     = (const float*)d_in[2];
    const float* a     = (const float*)d_in[3];
    const float* fcw   = (const float*)d_in[4];
    const float* fcb   = (const float*)d_in[5];
    const float* att   = (const float*)d_in[6];
    const float* adj   = (const float*)d_in[7];
    const int*   row   = (const int*)d_in[8];
    const int*   col   = (const int*)d_in[9];
    const int*   mask1 = (const int*)d_in[10];
    const int*   mask2 = (const int*)d_in[11];

    int n = in_sizes[0] / HDIM;
    int e = in_sizes[7];

    float* out   = (float*)d_out;
    float* z_mp  = out;
    float* z_mp2 = out + (size_t)n * HDIM;
    float* x_rec = out + (size_t)2 * n * HDIM;

    int gGemm = (n + 127) / 128;
    int gEW   = (n * 16 + 255) / 256;
    int gSp   = (n + 15) / 16;
    int gE4   = ((e + 3) / 4 + 255) / 256;
    int gN    = (n + 255) / 256;

    static cudaStream_t s2 = nullptr;
    static cudaEvent_t evFork = nullptr, evCsr = nullptr, evSpmm = nullptr,
                       evAtt0 = nullptr, evDone = nullptr;
    if (s2 == nullptr) {
        cudaStreamCreateWithFlags(&s2, cudaStreamNonBlocking);
        cudaEventCreateWithFlags(&evFork, cudaEventDisableTiming);
        cudaEventCreateWithFlags(&evCsr, cudaEventDisableTiming);
        cudaEventCreateWithFlags(&evSpmm, cudaEventDisableTiming);
        cudaEventCreateWithFlags(&evAtt0, cudaEventDisableTiming);
        cudaEventCreateWithFlags(&evDone, cudaEventDisableTiming);
    }
    cudaStream_t s0 = 0;

    // ---- fork: CSR build on s2, pass-1 GEMM on main (independent) ----
    cudaEventRecord(evFork, s0);
    cudaStreamWaitEvent(s2, evFork, 0);

    csr_zero<<<gN, 256, 0, s2>>>(n);
    csr_hist<<<gE4, 256, 0, s2>>>(row, e);
    csr_scan<<<1, 1024, 0, s2>>>(n);
    csr_scatter<<<gE4, 256, 0, s2>>>(row, col, adj, mask1, mask2, e);  // zeroes g_s
    cudaEventRecord(evCsr, s2);

    gemm_gcn_mma<<<gGemm, 128, 0, s0>>>(h, W, n);

    // ---- join: SpMM needs CSR + fts ----
    cudaStreamWaitEvent(s0, evCsr, 0);
    spmm_dual_all<<<gSp, 256, 0, s0>>>(b, n);
    cudaEventRecord(evSpmm, s0);

    // ---- branch B on s2: z_mp2 chain ----
    cudaStreamWaitEvent(s2, evSpmm, 0);
    att_gemm_mma<<<dim3(gGemm, PNUM), 128, 0, s2>>>(1, 1, a, fcw, fcb, n);
    combine_k<<<gEW, 256, 0, s2>>>(1, 1, a, att, z_mp2, n);

    // ---- main chain: att0 -> fused gemm3 (combine0 on s2) ----
    att_gemm_mma<<<dim3(gGemm, PNUM), 128, 0, s0>>>(0, 0, a, fcw, fcb, n);
    cudaEventRecord(evAtt0, s0);

    cudaStreamWaitEvent(s2, evAtt0, 0);
    combine_k<<<gEW, 256, 0, s2>>>(0, 0, a, att, z_mp, n);
    cudaEventRecord(evDone, s2);

    gemm_fused_z<<<gGemm, 128, 0, s0>>>(W, a, att, n);

    // spmm_mask overwrites embA -> wait for combine0 (s2) readers
    cudaStreamWaitEvent(s0, evDone, 0);
    spmm_mask_all<<<gSp, 256, 0, s0>>>(b, n);
    att_gemm_mma<<<dim3(gGemm, PNUM), 128, 0, s0>>>(2, 0, a, fcw, fcb, n);
    combine_k<<<gEW, 256, 0, s0>>>(2, 0, a, att, x_rec, n);
}

// round 15
// speedup vs baseline: 1.0156x; 1.0156x over previous
#include <cuda_runtime.h>
#include <cuda_fp16.h>
#include <stdint.h>
#include <math.h>

// Problem constants: N=100000, H=64, E=1600000, P=3
#define NMAX 100000
#define EMAX 1600000
#define HDIM 64
#define PNUM 3

// ---------------- scratch (no allocation allowed -> device globals) -------
__device__ __align__(16) __half g_fts16[PNUM][NMAX * HDIM];   // 38.4 MB
__device__ __align__(16) __half g_embA[PNUM][NMAX * HDIM];    // 19.2 MB (pass 1)
__device__ __align__(16) __half g_embB[PNUM][NMAX * HDIM];    // 19.2 MB (pass 2)
__device__ __align__(16) __half g_embC[PNUM][NMAX * HDIM];    // 19.2 MB (pass 3)
__device__ float g_s[3][PNUM * HDIM];   // slot 0: pass1(A), 1: pass2(B), 2: pass3(C)

// CSR scratch
__device__ int  g_deg[NMAX];
__device__ int  g_off[NMAX + 1];
__device__ int  g_cur[NMAX];
__device__ __align__(16) int2 g_edge[EMAX];   // .x = col | m1<<30 | m2<<31, .y = val bits

__device__ __forceinline__ float prelu_f(float x, float s) { return x > 0.f ? x : s * x; }

__device__ __forceinline__ uint32_t h2_bits(__half2 h)
{
    return *reinterpret_cast<uint32_t*>(&h);
}

// m16n8k16 row.col HMMA, fp16 inputs, fp32 accumulate
__device__ __forceinline__ void mma_16816(float* c, const uint32_t* a, const uint32_t* b)
{
    asm volatile("mma.sync.aligned.m16n8k16.row.col.f32.f16.f16.f32 "
                 "{%0,%1,%2,%3}, {%4,%5,%6,%7}, {%8,%9}, {%0,%1,%2,%3};"
                 : "+f"(c[0]), "+f"(c[1]), "+f"(c[2]), "+f"(c[3])
                 : "r"(a[0]), "r"(a[1]), "r"(a[2]), "r"(a[3]), "r"(b[0]), "r"(b[1]));
}

#define APAD 72   // padded half-stride: conflict-free 4B fragment loads

__device__ __forceinline__ float4 gath_mul(uint2 u, float v)
{
    float2 f01 = __half22float2(*(const __half2*)&u.x);
    float2 f23 = __half22float2(*(const __half2*)&u.y);
    return make_float4(f01.x * v, f01.y * v, f23.x * v, f23.y * v);
}
__device__ __forceinline__ uint2 pack_half4(float4 a)
{
    __half2 h0 = __floats2half2_rn(a.x, a.y);
    __half2 h1 = __floats2half2_rn(a.z, a.w);
    return make_uint2(h2_bits(h0), h2_bits(h1));
}

__device__ __forceinline__ const __half* emb_buf(int which, int p)
{
    return which == 0 ? g_embA[p] : (which == 1 ? g_embB[p] : g_embC[p]);
}

// per-block beta = softmax_p( (colsum_p . att) / n ) from g_s[slot]
__device__ __forceinline__ void block_beta(float* sbeta, int slot,
                                           const float* __restrict__ att, int n)
{
    int t = threadIdx.x;
    int w = t >> 5, l = t & 31;
    if (w < PNUM) {
        float v = g_s[slot][w * 64 + l] * __ldg(att + l)
                + g_s[slot][w * 64 + 32 + l] * __ldg(att + 32 + l);
#pragma unroll
        for (int o = 16; o; o >>= 1) v += __shfl_down_sync(0xffffffffu, v, o);
        if (l == 0) sbeta[w] = v / (float)n;
    }
    __syncthreads();
    if (t == 0) {
        float m = fmaxf(sbeta[0], fmaxf(sbeta[1], sbeta[2]));
        float e0 = expf(sbeta[0] - m), e1 = expf(sbeta[1] - m), e2 = expf(sbeta[2] - m);
        float inv = 1.f / (e0 + e1 + e2);
        sbeta[0] = e0 * inv; sbeta[1] = e1 * inv; sbeta[2] = e2 * inv;
    }
    __syncthreads();
}

// ===========================================================================
// CSR build
// ===========================================================================
__global__ void csr_zero(int n)
{
    int i = blockIdx.x * blockDim.x + threadIdx.x;
    if (i < n) g_deg[i] = 0;
}
__global__ void csr_hist(const int* __restrict__ row, int e)
{
    int i = blockIdx.x * blockDim.x + threadIdx.x;
    if (i < e) atomicAdd(&g_deg[row[i]], 1);
}
__global__ void csr_scan(int n)
{
    __shared__ int part[1024];
    int tid = threadIdx.x;
    int chunk = (n + 1023) >> 10;
    int beg = tid * chunk;
    int end = min(beg + chunk, n);
    int s = 0;
    for (int i = beg; i < end; i++) s += g_deg[i];
    part[tid] = s;
    __syncthreads();
    for (int o = 1; o < 1024; o <<= 1) {
        int t2 = (tid >= o) ? part[tid - o] : 0;
        __syncthreads();
        part[tid] += t2;
        __syncthreads();
    }
    int run = part[tid] - s;
    for (int i = beg; i < end; i++) {
        g_off[i] = run; g_cur[i] = run;
        run += g_deg[i];
    }
    if (tid == 1023) g_off[n] = part[1023];
}
__global__ void csr_scatter(const int* __restrict__ row, const int* __restrict__ col,
                            const float* __restrict__ vals,
                            const int* __restrict__ mask1, const int* __restrict__ mask2,
                            int e)
{
    if (blockIdx.x == 0 && threadIdx.x < PNUM * HDIM) {
        g_s[0][threadIdx.x] = 0.f;
        g_s[1][threadIdx.x] = 0.f;
        g_s[2][threadIdx.x] = 0.f;
    }
    int i = blockIdx.x * blockDim.x + threadIdx.x;
    if (i >= e) return;
    int r = __ldg(row + i), c = __ldg(col + i);
    float v = __ldg(vals + i);
    int fl = c | (__ldg(mask1 + c) ? (1 << 30) : 0) | (__ldg(mask2 + c) ? (1u << 31) : 0);
    int pos = atomicAdd(&g_cur[r], 1);
    g_edge[pos] = make_int2(fl, __float_as_int(v));
}

// ===========================================================================
// GCN GEMM via HMMA (fp32 input): loop p per 128-row tile
// ===========================================================================
__global__ __launch_bounds__(128) void gemm_gcn_mma(
    const float* __restrict__ X, const float* __restrict__ Wall, int n)
{
    __shared__ __half smA[128 * APAD];
    __shared__ __half smB[64 * APAD];

    int t = threadIdx.x, wid = t >> 5, lane = t & 31;
    int g = lane >> 2, q = lane & 3;
    int rowBase = blockIdx.x * 128;

#pragma unroll
    for (int i = 0; i < 16; i++) {
        int idx = t + i * 128;
        int r = idx >> 4, k4 = idx & 15;
        int gr = rowBase + r;
        float4 v = make_float4(0.f, 0.f, 0.f, 0.f);
        if (gr < n) v = __ldg(((const float4*)X) + gr * 16 + k4);
        __half* dst = &smA[r * APAD + k4 * 4];
        *(__half2*)(dst)     = __floats2half2_rn(v.x, v.y);
        *(__half2*)(dst + 2) = __floats2half2_rn(v.z, v.w);
    }

    for (int p = 0; p < PNUM; p++) {
        __syncthreads();
#pragma unroll
        for (int i = 0; i < 8; i++) {
            int idx = t + i * 128;
            int r = idx >> 4, k4 = idx & 15;
            float4 v = __ldg(((const float4*)(Wall + p * 4096)) + r * 16 + k4);
            __half* dst = &smB[r * APAD + k4 * 4];
            *(__half2*)(dst)     = __floats2half2_rn(v.x, v.y);
            *(__half2*)(dst + 2) = __floats2half2_rn(v.z, v.w);
        }
        __syncthreads();

        float acc[2][8][4];
#pragma unroll
        for (int mt = 0; mt < 2; mt++)
#pragma unroll
            for (int nt = 0; nt < 8; nt++)
#pragma unroll
                for (int c = 0; c < 4; c++) acc[mt][nt][c] = 0.f;

#pragma unroll
        for (int ks = 0; ks < 4; ks++) {
            uint32_t afr[2][4];
#pragma unroll
            for (int mt = 0; mt < 2; mt++) {
                int r0 = wid * 32 + mt * 16 + g;
                int kb = ks * 16 + q * 2;
                afr[mt][0] = *(const uint32_t*)&smA[r0 * APAD + kb];
                afr[mt][1] = *(const uint32_t*)&smA[(r0 + 8) * APAD + kb];
                afr[mt][2] = *(const uint32_t*)&smA[r0 * APAD + kb + 8];
                afr[mt][3] = *(const uint32_t*)&smA[(r0 + 8) * APAD + kb + 8];
            }
#pragma unroll
            for (int nt = 0; nt < 8; nt++) {
                int cb = (nt * 8 + g) * APAD + ks * 16 + q * 2;
                uint32_t bfr[2];
                bfr[0] = *(const uint32_t*)&smB[cb];
                bfr[1] = *(const uint32_t*)&smB[cb + 8];
                mma_16816(acc[0][nt], afr[0], bfr);
                mma_16816(acc[1][nt], afr[1], bfr);
            }
        }

        __half* F = g_fts16[p];
#pragma unroll
        for (int mt = 0; mt < 2; mt++) {
            int r0 = rowBase + wid * 32 + mt * 16 + g;
#pragma unroll
            for (int nt = 0; nt < 8; nt++) {
                int col = nt * 8 + q * 2;
                if (r0 < n)
                    *(__half2*)(F + (size_t)r0 * 64 + col) =
                        __floats2half2_rn(acc[mt][nt][0], acc[mt][nt][1]);
                if (r0 + 8 < n)
                    *(__half2*)(F + (size_t)(r0 + 8) * 64 + col) =
                        __floats2half2_rn(acc[mt][nt][2], acc[mt][nt][3]);
            }
        }
    }
}

// ===========================================================================
// Pass-3 GCN GEMM with FUSED combine: z = sum_p beta0_p*prelu(embA_p) built
// in-register per tile, then fts16[p] = z @ W[p]^T.
// ===========================================================================
__global__ __launch_bounds__(128) void gemm_fused_z(
    const float* __restrict__ Wall, const float* __restrict__ a,
    const float* __restrict__ att, int n)
{
    __shared__ __half smA[128 * APAD];
    __shared__ __half smB[64 * APAD];
    __shared__ float sbeta[PNUM];

    int t = threadIdx.x, wid = t >> 5, lane = t & 31;
    int g = lane >> 2, q = lane & 3;
    int rowBase = blockIdx.x * 128;

    block_beta(sbeta, 0, att, n);
    float b0 = sbeta[0], b1 = sbeta[1], b2 = sbeta[2];
    float s0 = __ldg(a), s1 = __ldg(a + 1), s2 = __ldg(a + 2);

#pragma unroll
    for (int i = 0; i < 16; i++) {
        int idx = t + i * 128;
        int r = idx >> 4, k4 = idx & 15;
        int gr = rowBase + r;
        float4 z = make_float4(0.f, 0.f, 0.f, 0.f);
        if (gr < n) {
            float4 e0 = gath_mul(*((const uint2*)(g_embA[0] + (size_t)gr * 64 + k4 * 4)), 1.f);
            float4 e1 = gath_mul(*((const uint2*)(g_embA[1] + (size_t)gr * 64 + k4 * 4)), 1.f);
            float4 e2 = gath_mul(*((const uint2*)(g_embA[2] + (size_t)gr * 64 + k4 * 4)), 1.f);
            z.x = b0 * prelu_f(e0.x, s0) + b1 * prelu_f(e1.x, s1) + b2 * prelu_f(e2.x, s2);
            z.y = b0 * prelu_f(e0.y, s0) + b1 * prelu_f(e1.y, s1) + b2 * prelu_f(e2.y, s2);
            z.z = b0 * prelu_f(e0.z, s0) + b1 * prelu_f(e1.z, s1) + b2 * prelu_f(e2.z, s2);
            z.w = b0 * prelu_f(e0.w, s0) + b1 * prelu_f(e1.w, s1) + b2 * prelu_f(e2.w, s2);
        }
        __half* dst = &smA[r * APAD + k4 * 4];
        *(__half2*)(dst)     = __floats2half2_rn(z.x, z.y);
        *(__half2*)(dst + 2) = __floats2half2_rn(z.z, z.w);
    }

    for (int p = 0; p < PNUM; p++) {
        __syncthreads();
#pragma unroll
        for (int i = 0; i < 8; i++) {
            int idx = t + i * 128;
            int r = idx >> 4, k4 = idx & 15;
            float4 v = __ldg(((const float4*)(Wall + p * 4096)) + r * 16 + k4);
            __half* dst = &smB[r * APAD + k4 * 4];
            *(__half2*)(dst)     = __floats2half2_rn(v.x, v.y);
            *(__half2*)(dst + 2) = __floats2half2_rn(v.z, v.w);
        }
        __syncthreads();

        float acc[2][8][4];
#pragma unroll
        for (int mt = 0; mt < 2; mt++)
#pragma unroll
            for (int nt = 0; nt < 8; nt++)
#pragma unroll
                for (int c = 0; c < 4; c++) acc[mt][nt][c] = 0.f;

#pragma unroll
        for (int ks = 0; ks < 4; ks++) {
            uint32_t afr[2][4];
#pragma unroll
            for (int mt = 0; mt < 2; mt++) {
                int r0 = wid * 32 + mt * 16 + g;
                int kb = ks * 16 + q * 2;
                afr[mt][0] = *(const uint32_t*)&smA[r0 * APAD + kb];
                afr[mt][1] = *(const uint32_t*)&smA[(r0 + 8) * APAD + kb];
                afr[mt][2] = *(const uint32_t*)&smA[r0 * APAD + kb + 8];
                afr[mt][3] = *(const uint32_t*)&smA[(r0 + 8) * APAD + kb + 8];
            }
#pragma unroll
            for (int nt = 0; nt < 8; nt++) {
                int cb = (nt * 8 + g) * APAD + ks * 16 + q * 2;
                uint32_t bfr[2];
                bfr[0] = *(const uint32_t*)&smB[cb];
                bfr[1] = *(const uint32_t*)&smB[cb + 8];
                mma_16816(acc[0][nt], afr[0], bfr);
                mma_16816(acc[1][nt], afr[1], bfr);
            }
        }

        __half* F = g_fts16[p];
#pragma unroll
        for (int mt = 0; mt < 2; mt++) {
            int r0 = rowBase + wid * 32 + mt * 16 + g;
#pragma unroll
            for (int nt = 0; nt < 8; nt++) {
                int col = nt * 8 + q * 2;
                if (r0 < n)
                    *(__half2*)(F + (size_t)r0 * 64 + col) =
                        __floats2half2_rn(acc[mt][nt][0], acc[mt][nt][1]);
                if (r0 + 8 < n)
                    *(__half2*)(F + (size_t)(r0 + 8) * 64 + col) =
                        __floats2half2_rn(acc[mt][nt][2], acc[mt][nt][3]);
            }
        }
    }
}

// ===========================================================================
// Attention GEMM via HMMA: grid = (tiles, p). slot selects g_s; buf selects emb
// ===========================================================================
__global__ __launch_bounds__(128) void att_gemm_mma(
    int slot, int buf, const float* __restrict__ a,
    const float* __restrict__ fcw, const float* __restrict__ fcb, int n)
{
    __shared__ __half smA[128 * APAD];
    __shared__ __half smB[64 * APAD];
    __shared__ float ssum[64];

    int t = threadIdx.x, wid = t >> 5, lane = t & 31;
    int g = lane >> 2, q = lane & 3;
    int rowBase = blockIdx.x * 128;
    int p = blockIdx.y;
    float sa = __ldg(a + p);
    const __half* E = emb_buf(buf, p);

    if (t < 64) ssum[t] = 0.f;

#pragma unroll
    for (int i = 0; i < 16; i++) {
        int idx = t + i * 128;
        int r = idx >> 4, k4 = idx & 15;
        int gr = rowBase + r;
        float4 v = make_float4(0.f, 0.f, 0.f, 0.f);
        if (gr < n) {
            uint2 u = *((const uint2*)(E + (size_t)gr * 64 + k4 * 4));
            float2 f01 = __half22float2(*(__half2*)&u.x);
            float2 f23 = __half22float2(*(__half2*)&u.y);
            v.x = prelu_f(f01.x, sa); v.y = prelu_f(f01.y, sa);
            v.z = prelu_f(f23.x, sa); v.w = prelu_f(f23.y, sa);
        }
        __half* dst = &smA[r * APAD + k4 * 4];
        *(__half2*)(dst)     = __floats2half2_rn(v.x, v.y);
        *(__half2*)(dst + 2) = __floats2half2_rn(v.z, v.w);
    }
#pragma unroll
    for (int i = 0; i < 8; i++) {
        int idx = t + i * 128;
        int r = idx >> 4, k4 = idx & 15;
        float4 v = __ldg(((const float4*)fcw) + r * 16 + k4);
        __half* dst = &smB[r * APAD + k4 * 4];
        *(__half2*)(dst)     = __floats2half2_rn(v.x, v.y);
        *(__half2*)(dst + 2) = __floats2half2_rn(v.z, v.w);
    }
    __syncthreads();

    float acc[2][8][4];
#pragma unroll
    for (int mt = 0; mt < 2; mt++)
#pragma unroll
        for (int nt = 0; nt < 8; nt++)
#pragma unroll
            for (int c = 0; c < 4; c++) acc[mt][nt][c] = 0.f;

#pragma unroll
    for (int ks = 0; ks < 4; ks++) {
        uint32_t afr[2][4];
#pragma unroll
        for (int mt = 0; mt < 2; mt++) {
            int r0 = wid * 32 + mt * 16 + g;
            int kb = ks * 16 + q * 2;
            afr[mt][0] = *(const uint32_t*)&smA[r0 * APAD + kb];
            afr[mt][1] = *(const uint32_t*)&smA[(r0 + 8) * APAD + kb];
            afr[mt][2] = *(const uint32_t*)&smA[r0 * APAD + kb + 8];
            afr[mt][3] = *(const uint32_t*)&smA[(r0 + 8) * APAD + kb + 8];
        }
#pragma unroll
        for (int nt = 0; nt < 8; nt++) {
            int cb = (nt * 8 + g) * APAD + ks * 16 + q * 2;
            uint32_t bfr[2];
            bfr[0] = *(const uint32_t*)&smB[cb];
            bfr[1] = *(const uint32_t*)&smB[cb + 8];
            mma_16816(acc[0][nt], afr[0], bfr);
            mma_16816(acc[1][nt], afr[1], bfr);
        }
    }

    float colsum[16];
#pragma unroll
    for (int i = 0; i < 16; i++) colsum[i] = 0.f;
#pragma unroll
    for (int mt = 0; mt < 2; mt++) {
        int r0 = rowBase + wid * 32 + mt * 16 + g;
#pragma unroll
        for (int nt = 0; nt < 8; nt++) {
            int col = nt * 8 + q * 2;
            float fb0 = __ldg(fcb + col), fb1 = __ldg(fcb + col + 1);
            if (r0 < n) {
                colsum[nt * 2]     += tanhf(acc[mt][nt][0] + fb0);
                colsum[nt * 2 + 1] += tanhf(acc[mt][nt][1] + fb1);
            }
            if (r0 + 8 < n) {
                colsum[nt * 2]     += tanhf(acc[mt][nt][2] + fb0);
                colsum[nt * 2 + 1] += tanhf(acc[mt][nt][3] + fb1);
            }
        }
    }
#pragma unroll
    for (int o = 4; o < 32; o <<= 1) {
#pragma unroll
        for (int i = 0; i < 16; i++)
            colsum[i] += __shfl_xor_sync(0xffffffffu, colsum[i], o);
    }
    if (lane < 4) {
#pragma unroll
        for (int nt = 0; nt < 8; nt++) {
            atomicAdd(&ssum[nt * 8 + q * 2], colsum[nt * 2]);
            atomicAdd(&ssum[nt * 8 + q * 2 + 1], colsum[nt * 2 + 1]);
        }
    }
    __syncthreads();
    if (t < 64) atomicAdd(&g_s[slot][p * 64 + t], ssum[t]);
}

// ===========================================================================
// CSR SpMM (R9 shape: 16 lanes/row, 16 rows per 256-thread block)
// ===========================================================================
__global__ __launch_bounds__(256) void spmm_dual_all(const float* __restrict__ b, int n)
{
    int rr = blockIdx.x * 16 + (threadIdx.x >> 4);
    int l = threadIdx.x & 15;
    if (rr >= n) return;
    int beg = g_off[rr], end = g_off[rr + 1];

    float4 aA[PNUM], aB[PNUM];
#pragma unroll
    for (int p = 0; p < PNUM; p++) {
        float4 bias = __ldg(((const float4*)(b + p * HDIM)) + l);
        aA[p] = bias; aB[p] = bias;
    }

    int i = beg;
#pragma unroll 1
    for (; i + 4 <= end; i += 4) {
        int2 ed[4];
#pragma unroll
        for (int j = 0; j < 4; j++) ed[j] = __ldg(g_edge + i + j);
        uint2 u[4][PNUM];
#pragma unroll
        for (int j = 0; j < 4; j++) {
            int c = ed[j].x & 0xFFFFFF;
#pragma unroll
            for (int p = 0; p < PNUM; p++)
                u[j][p] = __ldg(((const uint2*)g_fts16[p]) + c * 16 + l);
        }
#pragma unroll
        for (int j = 0; j < 4; j++) {
            float v = __int_as_float(ed[j].y);
            float sA = (ed[j].x & (1 << 30)) ? 0.f : 1.f;
#pragma unroll
            for (int p = 0; p < PNUM; p++) {
                float4 f = gath_mul(u[j][p], v);
                aB[p].x += f.x; aB[p].y += f.y; aB[p].z += f.z; aB[p].w += f.w;
                aA[p].x = fmaf(f.x, sA, aA[p].x);
                aA[p].y = fmaf(f.y, sA, aA[p].y);
                aA[p].z = fmaf(f.z, sA, aA[p].z);
                aA[p].w = fmaf(f.w, sA, aA[p].w);
            }
        }
    }
#pragma unroll 1
    for (; i < end; i++) {
        int2 ed = __ldg(g_edge + i);
        int c = ed.x & 0xFFFFFF;
        float v = __int_as_float(ed.y);
        float sA = (ed.x & (1 << 30)) ? 0.f : 1.f;
#pragma unroll
        for (int p = 0; p < PNUM; p++) {
            uint2 u = __ldg(((const uint2*)g_fts16[p]) + c * 16 + l);
            float4 f = gath_mul(u, v);
            aB[p].x += f.x; aB[p].y += f.y; aB[p].z += f.z; aB[p].w += f.w;
            aA[p].x = fmaf(f.x, sA, aA[p].x);
            aA[p].y = fmaf(f.y, sA, aA[p].y);
            aA[p].z = fmaf(f.z, sA, aA[p].z);
            aA[p].w = fmaf(f.w, sA, aA[p].w);
        }
    }
#pragma unroll
    for (int p = 0; p < PNUM; p++) {
        ((uint2*)g_embA[p])[rr * 16 + l] = pack_half4(aA[p]);
        ((uint2*)g_embB[p])[rr * 16 + l] = pack_half4(aB[p]);
    }
}

// Pass-3 SpMM: skip gathers for mask2 edges; writes embC (no conflict with combine0)
__global__ __launch_bounds__(256) void spmm_mask_all(const float* __restrict__ b, int n)
{
    int rr = blockIdx.x * 16 + (threadIdx.x >> 4);
    int l = threadIdx.x & 15;
    if (rr >= n) return;
    int beg = g_off[rr], end = g_off[rr + 1];

    float4 aA[PNUM];
#pragma unroll
    for (int p = 0; p < PNUM; p++)
        aA[p] = __ldg(((const float4*)(b + p * HDIM)) + l);

    int i = beg;
#pragma unroll 1
    for (; i + 4 <= end; i += 4) {
        int2 ed[4];
#pragma unroll
        for (int j = 0; j < 4; j++) ed[j] = __ldg(g_edge + i + j);
#pragma unroll
        for (int j = 0; j < 4; j++) {
            if (ed[j].x & (1u << 31)) continue;
            int c = ed[j].x & 0xFFFFFF;
            float v = __int_as_float(ed[j].y);
#pragma unroll
            for (int p = 0; p < PNUM; p++) {
                uint2 u = __ldg(((const uint2*)g_fts16[p]) + c * 16 + l);
                float4 f = gath_mul(u, v);
                aA[p].x += f.x; aA[p].y += f.y; aA[p].z += f.z; aA[p].w += f.w;
            }
        }
    }
#pragma unroll 1
    for (; i < end; i++) {
        int2 ed = __ldg(g_edge + i);
        if (ed.x & (1u << 31)) continue;
        int c = ed.x & 0xFFFFFF;
        float v = __int_as_float(ed.y);
#pragma unroll
        for (int p = 0; p < PNUM; p++) {
            uint2 u = __ldg(((const uint2*)g_fts16[p]) + c * 16 + l);
            float4 f = gath_mul(u, v);
            aA[p].x += f.x; aA[p].y += f.y; aA[p].z += f.z; aA[p].w += f.w;
        }
    }
#pragma unroll
    for (int p = 0; p < PNUM; p++)
        ((uint2*)g_embC[p])[rr * 16 + l] = pack_half4(aA[p]);
}

// ===========================================================================
// combine: inline softmax(beta) from g_s[slot], then weighted prelu-combine
// ===========================================================================
__global__ void combine_k(int slot, int buf, const float* __restrict__ a,
                          const float* __restrict__ att, float* __restrict__ out, int n)
{
    __shared__ float sbeta[PNUM];
    block_beta(sbeta, slot, att, n);

    int idx = blockIdx.x * blockDim.x + threadIdx.x;
    if (idx >= n * 16) return;
    float b0 = sbeta[0], b1 = sbeta[1], b2 = sbeta[2];
    float s0 = __ldg(a), s1 = __ldg(a + 1), s2 = __ldg(a + 2);
    const uint2* E0 = (const uint2*)emb_buf(buf, 0);
    const uint2* E1 = (const uint2*)emb_buf(buf, 1);
    const uint2* E2 = (const uint2*)emb_buf(buf, 2);
    float4 e0 = gath_mul(E0[idx], 1.f);
    float4 e1 = gath_mul(E1[idx], 1.f);
    float4 e2 = gath_mul(E2[idx], 1.f);
    float4 o;
    o.x = b0 * prelu_f(e0.x, s0) + b1 * prelu_f(e1.x, s1) + b2 * prelu_f(e2.x, s2);
    o.y = b0 * prelu_f(e0.y, s0) + b1 * prelu_f(e1.y, s1) + b2 * prelu_f(e2.y, s2);
    o.z = b0 * prelu_f(e0.z, s0) + b1 * prelu_f(e1.z, s1) + b2 * prelu_f(e2.z, s2);
    o.w = b0 * prelu_f(e0.w, s0) + b1 * prelu_f(e1.w, s1) + b2 * prelu_f(e2.w, s2);
    ((float4*)out)[idx] = o;
}

// ===========================================================================
extern "C" void kernel_launch(void* const* d_in, const int* in_sizes, int n_in,
                              void* d_out, int out_size)
{
    const float* h     = (const float*)d_in[0];
    const float* W     = (const float*)d_in[1];
    const float* b     = (const float*)d_in[2];
    const float* a     = (const float*)d_in[3];
    const float* fcw   = (const float*)d_in[4];
    const float* fcb   = (const float*)d_in[5];
    const float* att   = (const float*)d_in[6];
    const float* adj   = (const float*)d_in[7];
    const int*   row   = (const int*)d_in[8];
    const int*   col   = (const int*)d_in[9];
    const int*   mask1 = (const int*)d_in[10];
    const int*   mask2 = (const int*)d_in[11];

    int n = in_sizes[0] / HDIM;
    int e = in_sizes[7];

    float* out   = (float*)d_out;
    float* z_mp  = out;
    float* z_mp2 = out + (size_t)n * HDIM;
    float* x_rec = out + (size_t)2 * n * HDIM;

    int gGemm = (n + 127) / 128;
    int gEW   = (n * 16 + 255) / 256;
    int gSp   = (n + 15) / 16;
    int gE    = (e + 255) / 256;
    int gN    = (n + 255) / 256;

    static cudaStream_t s2 = nullptr;
    static cudaEvent_t evFork = nullptr, evCsr = nullptr, evSpmm = nullptr,
                       evAtt0 = nullptr, evDone = nullptr;
    if (s2 == nullptr) {
        cudaStreamCreateWithFlags(&s2, cudaStreamNonBlocking);
        cudaEventCreateWithFlags(&evFork, cudaEventDisableTiming);
        cudaEventCreateWithFlags(&evCsr, cudaEventDisableTiming);
        cudaEventCreateWithFlags(&evSpmm, cudaEventDisableTiming);
        cudaEventCreateWithFlags(&evAtt0, cudaEventDisableTiming);
        cudaEventCreateWithFlags(&evDone, cudaEventDisableTiming);
    }
    cudaStream_t s0 = 0;

    // ---- fork: CSR build on s2, pass-1 GEMM on main (independent) ----
    cudaEventRecord(evFork, s0);
    cudaStreamWaitEvent(s2, evFork, 0);

    csr_zero<<<gN, 256, 0, s2>>>(n);
    csr_hist<<<gE, 256, 0, s2>>>(row, e);
    csr_scan<<<1, 1024, 0, s2>>>(n);
    csr_scatter<<<gE, 256, 0, s2>>>(row, col, adj, mask1, mask2, e);  // zeroes g_s
    cudaEventRecord(evCsr, s2);

    gemm_gcn_mma<<<gGemm, 128, 0, s0>>>(h, W, n);

    // ---- join: SpMM needs CSR + fts ----
    cudaStreamWaitEvent(s0, evCsr, 0);
    spmm_dual_all<<<gSp, 256, 0, s0>>>(b, n);
    cudaEventRecord(evSpmm, s0);

    // ---- branch B on s2: z_mp2 chain ----
    cudaStreamWaitEvent(s2, evSpmm, 0);
    att_gemm_mma<<<dim3(gGemm, PNUM), 128, 0, s2>>>(1, 1, a, fcw, fcb, n);
    combine_k<<<gEW, 256, 0, s2>>>(1, 1, a, att, z_mp2, n);

    // ---- main chain: att0 -> fused gemm3 -> pass-3 (embC; combine0 on s2) ----
    att_gemm_mma<<<dim3(gGemm, PNUM), 128, 0, s0>>>(0, 0, a, fcw, fcb, n);
    cudaEventRecord(evAtt0, s0);

    // combine0 on s2: reads embA + g_s[0], fully off the critical path now
    cudaStreamWaitEvent(s2, evAtt0, 0);
    combine_k<<<gEW, 256, 0, s2>>>(0, 0, a, att, z_mp, n);
    cudaEventRecord(evDone, s2);

    gemm_fused_z<<<gGemm, 128, 0, s0>>>(W, a, att, n);
    spmm_mask_all<<<gSp, 256, 0, s0>>>(b, n);               // writes embC (no wait!)
    att_gemm_mma<<<dim3(gGemm, PNUM), 128, 0, s0>>>(2, 2, a, fcw, fcb, n);
    combine_k<<<gEW, 256, 0, s0>>>(2, 2, a, att, x_rec, n);

    // ---- final join: graph completes only after s2 branch (z_mp, z_mp2) ----
    cudaStreamWaitEvent(s0, evDone, 0);
}

// round 16
// speedup vs baseline: 1.0356x; 1.0197x over previous
#include <cuda_runtime.h>
#include <cuda_fp16.h>
#include <stdint.h>
#include <math.h>

// Problem constants: N=100000, H=64, E=1600000, P=3
#define NMAX 100000
#define EMAX 1600000
#define HDIM 64
#define PNUM 3

// ---------------- scratch (no allocation allowed -> device globals) -------
__device__ __align__(16) __half g_fts16[PNUM][NMAX * HDIM];   // 38.4 MB
__device__ __align__(16) __half g_embA[PNUM][NMAX * HDIM];    // 19.2 MB
__device__ __align__(16) __half g_embB[PNUM][NMAX * HDIM];    // 19.2 MB
__device__ __align__(16) __half g_z16[NMAX * HDIM];           // 12.8 MB (z_mp fp16)
__device__ float g_s[2][PNUM * HDIM];

// CSR scratch
__device__ int  g_deg[NMAX];
__device__ int  g_off[NMAX + 1];
__device__ int  g_cur[NMAX];
__device__ __align__(16) int2 g_edge[EMAX];   // .x = col | m1<<30 | m2<<31, .y = val bits

__device__ __forceinline__ float prelu_f(float x, float s) { return x > 0.f ? x : s * x; }

__device__ __forceinline__ uint32_t h2_bits(__half2 h)
{
    return *reinterpret_cast<uint32_t*>(&h);
}

// m16n8k16 row.col HMMA, fp16 inputs, fp32 accumulate
__device__ __forceinline__ void mma_16816(float* c, const uint32_t* a, const uint32_t* b)
{
    asm volatile("mma.sync.aligned.m16n8k16.row.col.f32.f16.f16.f32 "
                 "{%0,%1,%2,%3}, {%4,%5,%6,%7}, {%8,%9}, {%0,%1,%2,%3};"
                 : "+f"(c[0]), "+f"(c[1]), "+f"(c[2]), "+f"(c[3])
                 : "r"(a[0]), "r"(a[1]), "r"(a[2]), "r"(a[3]), "r"(b[0]), "r"(b[1]));
}

#define APAD 72   // padded half-stride: conflict-free 4B fragment loads

__device__ __forceinline__ float4 gath_mul(uint2 u, float v)
{
    float2 f01 = __half22float2(*(const __half2*)&u.x);
    float2 f23 = __half22float2(*(const __half2*)&u.y);
    return make_float4(f01.x * v, f01.y * v, f23.x * v, f23.y * v);
}
__device__ __forceinline__ uint2 pack_half4(float4 a)
{
    __half2 h0 = __floats2half2_rn(a.x, a.y);
    __half2 h1 = __floats2half2_rn(a.z, a.w);
    return make_uint2(h2_bits(h0), h2_bits(h1));
}

// ===========================================================================
// CSR build (streaming loads use __ldcs: no reuse within/between launches
// matters less than keeping fts/emb resident in L2)
// ===========================================================================
__global__ void csr_zero(int n)
{
    int i = blockIdx.x * blockDim.x + threadIdx.x;
    if (i < n) g_deg[i] = 0;
}
__global__ void csr_hist(const int* __restrict__ row, int e)
{
    int i = blockIdx.x * blockDim.x + threadIdx.x;
    if (i < e) atomicAdd(&g_deg[__ldcs(row + i)], 1);
}
__global__ void csr_scan(int n)
{
    __shared__ int part[1024];
    int tid = threadIdx.x;
    int chunk = (n + 1023) >> 10;
    int beg = tid * chunk;
    int end = min(beg + chunk, n);
    int s = 0;
    for (int i = beg; i < end; i++) s += g_deg[i];
    part[tid] = s;
    __syncthreads();
    for (int o = 1; o < 1024; o <<= 1) {
        int t2 = (tid >= o) ? part[tid - o] : 0;
        __syncthreads();
        part[tid] += t2;
        __syncthreads();
    }
    int run = part[tid] - s;
    for (int i = beg; i < end; i++) {
        g_off[i] = run; g_cur[i] = run;
        run += g_deg[i];
    }
    if (tid == 1023) g_off[n] = part[1023];
}
__global__ void csr_scatter(const int* __restrict__ row, const int* __restrict__ col,
                            const float* __restrict__ vals,
                            const int* __restrict__ mask1, const int* __restrict__ mask2,
                            int e)
{
    int i = blockIdx.x * blockDim.x + threadIdx.x;
    if (i >= e) return;
    int r = __ldcs(row + i), c = __ldcs(col + i);
    float v = __ldcs(vals + i);
    int fl = c | (__ldg(mask1 + c) ? (1 << 30) : 0) | (__ldg(mask2 + c) ? (1u << 31) : 0);
    int pos = atomicAdd(&g_cur[r], 1);
    g_edge[pos] = make_int2(fl, __float_as_int(v));
}

// ===========================================================================
// GCN GEMM via HMMA (fp32 input): loop p per 128-row tile
// ===========================================================================
__global__ __launch_bounds__(128) void gemm_gcn_mma(
    const float* __restrict__ X, const float* __restrict__ Wall, int n)
{
    __shared__ __half smA[128 * APAD];
    __shared__ __half smB[64 * APAD];

    int t = threadIdx.x, wid = t >> 5, lane = t & 31;
    int g = lane >> 2, q = lane & 3;
    int rowBase = blockIdx.x * 128;

#pragma unroll
    for (int i = 0; i < 16; i++) {
        int idx = t + i * 128;
        int r = idx >> 4, k4 = idx & 15;
        int gr = rowBase + r;
        float4 v = make_float4(0.f, 0.f, 0.f, 0.f);
        if (gr < n) v = __ldg(((const float4*)X) + gr * 16 + k4);
        __half* dst = &smA[r * APAD + k4 * 4];
        *(__half2*)(dst)     = __floats2half2_rn(v.x, v.y);
        *(__half2*)(dst + 2) = __floats2half2_rn(v.z, v.w);
    }

    for (int p = 0; p < PNUM; p++) {
        __syncthreads();
#pragma unroll
        for (int i = 0; i < 8; i++) {
            int idx = t + i * 128;
            int r = idx >> 4, k4 = idx & 15;
            float4 v = __ldg(((const float4*)(Wall + p * 4096)) + r * 16 + k4);
            __half* dst = &smB[r * APAD + k4 * 4];
            *(__half2*)(dst)     = __floats2half2_rn(v.x, v.y);
            *(__half2*)(dst + 2) = __floats2half2_rn(v.z, v.w);
        }
        __syncthreads();

        float acc[2][8][4];
#pragma unroll
        for (int mt = 0; mt < 2; mt++)
#pragma unroll
            for (int nt = 0; nt < 8; nt++)
#pragma unroll
                for (int c = 0; c < 4; c++) acc[mt][nt][c] = 0.f;

#pragma unroll
        for (int ks = 0; ks < 4; ks++) {
            uint32_t afr[2][4];
#pragma unroll
            for (int mt = 0; mt < 2; mt++) {
                int r0 = wid * 32 + mt * 16 + g;
                int kb = ks * 16 + q * 2;
                afr[mt][0] = *(const uint32_t*)&smA[r0 * APAD + kb];
                afr[mt][1] = *(const uint32_t*)&smA[(r0 + 8) * APAD + kb];
                afr[mt][2] = *(const uint32_t*)&smA[r0 * APAD + kb + 8];
                afr[mt][3] = *(const uint32_t*)&smA[(r0 + 8) * APAD + kb + 8];
            }
#pragma unroll
            for (int nt = 0; nt < 8; nt++) {
                int cb = (nt * 8 + g) * APAD + ks * 16 + q * 2;
                uint32_t bfr[2];
                bfr[0] = *(const uint32_t*)&smB[cb];
                bfr[1] = *(const uint32_t*)&smB[cb + 8];
                mma_16816(acc[0][nt], afr[0], bfr);
                mma_16816(acc[1][nt], afr[1], bfr);
            }
        }

        __half* F = g_fts16[p];
#pragma unroll
        for (int mt = 0; mt < 2; mt++) {
            int r0 = rowBase + wid * 32 + mt * 16 + g;
#pragma unroll
            for (int nt = 0; nt < 8; nt++) {
                int col = nt * 8 + q * 2;
                if (r0 < n)
                    *(__half2*)(F + (size_t)r0 * 64 + col) =
                        __floats2half2_rn(acc[mt][nt][0], acc[mt][nt][1]);
                if (r0 + 8 < n)
                    *(__half2*)(F + (size_t)(r0 + 8) * 64 + col) =
                        __floats2half2_rn(acc[mt][nt][2], acc[mt][nt][3]);
            }
        }
    }
}

// fp16-input variant (pass 3: reads g_z16 directly)
__global__ __launch_bounds__(128) void gemm_gcn_mma_h(
    const float* __restrict__ Wall, int n)
{
    __shared__ __half smA[128 * APAD];
    __shared__ __half smB[64 * APAD];

    int t = threadIdx.x, wid = t >> 5, lane = t & 31;
    int g = lane >> 2, q = lane & 3;
    int rowBase = blockIdx.x * 128;

#pragma unroll
    for (int i = 0; i < 16; i++) {
        int idx = t + i * 128;
        int r = idx >> 4, k4 = idx & 15;
        int gr = rowBase + r;
        uint2 u = make_uint2(0u, 0u);
        if (gr < n) u = *((const uint2*)(g_z16 + (size_t)gr * 64 + k4 * 4));
        *(uint2*)&smA[r * APAD + k4 * 4] = u;
    }

    for (int p = 0; p < PNUM; p++) {
        __syncthreads();
#pragma unroll
        for (int i = 0; i < 8; i++) {
            int idx = t + i * 128;
            int r = idx >> 4, k4 = idx & 15;
            float4 v = __ldg(((const float4*)(Wall + p * 4096)) + r * 16 + k4);
            __half* dst = &smB[r * APAD + k4 * 4];
            *(__half2*)(dst)     = __floats2half2_rn(v.x, v.y);
            *(__half2*)(dst + 2) = __floats2half2_rn(v.z, v.w);
        }
        __syncthreads();

        float acc[2][8][4];
#pragma unroll
        for (int mt = 0; mt < 2; mt++)
#pragma unroll
            for (int nt = 0; nt < 8; nt++)
#pragma unroll
                for (int c = 0; c < 4; c++) acc[mt][nt][c] = 0.f;

#pragma unroll
        for (int ks = 0; ks < 4; ks++) {
            uint32_t afr[2][4];
#pragma unroll
            for (int mt = 0; mt < 2; mt++) {
                int r0 = wid * 32 + mt * 16 + g;
                int kb = ks * 16 + q * 2;
                afr[mt][0] = *(const uint32_t*)&smA[r0 * APAD + kb];
                afr[mt][1] = *(const uint32_t*)&smA[(r0 + 8) * APAD + kb];
                afr[mt][2] = *(const uint32_t*)&smA[r0 * APAD + kb + 8];
                afr[mt][3] = *(const uint32_t*)&smA[(r0 + 8) * APAD + kb + 8];
            }
#pragma unroll
            for (int nt = 0; nt < 8; nt++) {
                int cb = (nt * 8 + g) * APAD + ks * 16 + q * 2;
                uint32_t bfr[2];
                bfr[0] = *(const uint32_t*)&smB[cb];
                bfr[1] = *(const uint32_t*)&smB[cb + 8];
                mma_16816(acc[0][nt], afr[0], bfr);
                mma_16816(acc[1][nt], afr[1], bfr);
            }
        }

        __half* F = g_fts16[p];
#pragma unroll
        for (int mt = 0; mt < 2; mt++) {
            int r0 = rowBase + wid * 32 + mt * 16 + g;
#pragma unroll
            for (int nt = 0; nt < 8; nt++) {
                int col = nt * 8 + q * 2;
                if (r0 < n)
                    *(__half2*)(F + (size_t)r0 * 64 + col) =
                        __floats2half2_rn(acc[mt][nt][0], acc[mt][nt][1]);
                if (r0 + 8 < n)
                    *(__half2*)(F + (size_t)(r0 + 8) * 64 + col) =
                        __floats2half2_rn(acc[mt][nt][2], acc[mt][nt][3]);
            }
        }
    }
}

// ===========================================================================
// Attention GEMM via HMMA (fp16 emb input): grid = (tiles, p), sel as arg
// ===========================================================================
__global__ __launch_bounds__(128) void att_gemm_mma(
    int sel, const float* __restrict__ a,
    const float* __restrict__ fcw, const float* __restrict__ fcb, int n)
{
    __shared__ __half smA[128 * APAD];
    __shared__ __half smB[64 * APAD];
    __shared__ float ssum[64];

    int t = threadIdx.x, wid = t >> 5, lane = t & 31;
    int g = lane >> 2, q = lane & 3;
    int rowBase = blockIdx.x * 128;
    int p = blockIdx.y;
    float sa = __ldg(a + p);
    const __half* E = (sel == 0) ? g_embA[p] : g_embB[p];

    if (t < 64) ssum[t] = 0.f;

#pragma unroll
    for (int i = 0; i < 16; i++) {
        int idx = t + i * 128;
        int r = idx >> 4, k4 = idx & 15;
        int gr = rowBase + r;
        float4 v = make_float4(0.f, 0.f, 0.f, 0.f);
        if (gr < n) {
            uint2 u = *((const uint2*)(E + (size_t)gr * 64 + k4 * 4));
            float2 f01 = __half22float2(*(__half2*)&u.x);
            float2 f23 = __half22float2(*(__half2*)&u.y);
            v.x = prelu_f(f01.x, sa); v.y = prelu_f(f01.y, sa);
            v.z = prelu_f(f23.x, sa); v.w = prelu_f(f23.y, sa);
        }
        __half* dst = &smA[r * APAD + k4 * 4];
        *(__half2*)(dst)     = __floats2half2_rn(v.x, v.y);
        *(__half2*)(dst + 2) = __floats2half2_rn(v.z, v.w);
    }
#pragma unroll
    for (int i = 0; i < 8; i++) {
        int idx = t + i * 128;
        int r = idx >> 4, k4 = idx & 15;
        float4 v = __ldg(((const float4*)fcw) + r * 16 + k4);
        __half* dst = &smB[r * APAD + k4 * 4];
        *(__half2*)(dst)     = __floats2half2_rn(v.x, v.y);
        *(__half2*)(dst + 2) = __floats2half2_rn(v.z, v.w);
    }
    __syncthreads();

    float acc[2][8][4];
#pragma unroll
    for (int mt = 0; mt < 2; mt++)
#pragma unroll
        for (int nt = 0; nt < 8; nt++)
#pragma unroll
            for (int c = 0; c < 4; c++) acc[mt][nt][c] = 0.f;

#pragma unroll
    for (int ks = 0; ks < 4; ks++) {
        uint32_t afr[2][4];
#pragma unroll
        for (int mt = 0; mt < 2; mt++) {
            int r0 = wid * 32 + mt * 16 + g;
            int kb = ks * 16 + q * 2;
            afr[mt][0] = *(const uint32_t*)&smA[r0 * APAD + kb];
            afr[mt][1] = *(const uint32_t*)&smA[(r0 + 8) * APAD + kb];
            afr[mt][2] = *(const uint32_t*)&smA[r0 * APAD + kb + 8];
            afr[mt][3] = *(const uint32_t*)&smA[(r0 + 8) * APAD + kb + 8];
        }
#pragma unroll
        for (int nt = 0; nt < 8; nt++) {
            int cb = (nt * 8 + g) * APAD + ks * 16 + q * 2;
            uint32_t bfr[2];
            bfr[0] = *(const uint32_t*)&smB[cb];
            bfr[1] = *(const uint32_t*)&smB[cb + 8];
            mma_16816(acc[0][nt], afr[0], bfr);
            mma_16816(acc[1][nt], afr[1], bfr);
        }
    }

    float colsum[16];
#pragma unroll
    for (int i = 0; i < 16; i++) colsum[i] = 0.f;
#pragma unroll
    for (int mt = 0; mt < 2; mt++) {
        int r0 = rowBase + wid * 32 + mt * 16 + g;
#pragma unroll
        for (int nt = 0; nt < 8; nt++) {
            int col = nt * 8 + q * 2;
            float fb0 = __ldg(fcb + col), fb1 = __ldg(fcb + col + 1);
            if (r0 < n) {
                colsum[nt * 2]     += tanhf(acc[mt][nt][0] + fb0);
                colsum[nt * 2 + 1] += tanhf(acc[mt][nt][1] + fb1);
            }
            if (r0 + 8 < n) {
                colsum[nt * 2]     += tanhf(acc[mt][nt][2] + fb0);
                colsum[nt * 2 + 1] += tanhf(acc[mt][nt][3] + fb1);
            }
        }
    }
#pragma unroll
    for (int o = 4; o < 32; o <<= 1) {
#pragma unroll
        for (int i = 0; i < 16; i++)
            colsum[i] += __shfl_xor_sync(0xffffffffu, colsum[i], o);
    }
    if (lane < 4) {
#pragma unroll
        for (int nt = 0; nt < 8; nt++) {
            atomicAdd(&ssum[nt * 8 + q * 2], colsum[nt * 2]);
            atomicAdd(&ssum[nt * 8 + q * 2 + 1], colsum[nt * 2 + 1]);
        }
    }
    __syncthreads();
    if (t < 64) atomicAdd(&g_s[sel][p * 64 + t], ssum[t]);
}

// ===========================================================================
// CSR SpMM: 16 lanes/row, 4-edge batching, branchless masking. Edge stream
// loaded with __ldcs (evict-first) so fts16 keeps L1/L2 residency.
// ===========================================================================
__global__ __launch_bounds__(256) void spmm_dual_all(const float* __restrict__ b, int n)
{
    if (blockIdx.x == 0 && threadIdx.x < PNUM * HDIM) {
        g_s[0][threadIdx.x] = 0.f;
        g_s[1][threadIdx.x] = 0.f;
    }

    int rr = blockIdx.x * 16 + (threadIdx.x >> 4);
    int l = threadIdx.x & 15;
    if (rr >= n) return;
    int beg = g_off[rr], end = g_off[rr + 1];

    float4 aA[PNUM], aB[PNUM];
#pragma unroll
    for (int p = 0; p < PNUM; p++) {
        float4 bias = __ldg(((const float4*)(b + p * HDIM)) + l);
        aA[p] = bias; aB[p] = bias;
    }
#pragma unroll 4
    for (int i = beg; i < end; i++) {
        int2 ed = __ldcs(g_edge + i);
        int c = ed.x & 0xFFFFFF;
        float v = __int_as_float(ed.y);
        bool m1 = (ed.x & (1 << 30)) != 0;
        uint2 u[PNUM];
#pragma unroll
        for (int p = 0; p < PNUM; p++)
            u[p] = __ldg(((const uint2*)g_fts16[p]) + c * 16 + l);
        float sA = m1 ? 0.f : 1.f;
#pragma unroll
        for (int p = 0; p < PNUM; p++) {
            float4 f = gath_mul(u[p], v);
            aB[p].x += f.x; aB[p].y += f.y; aB[p].z += f.z; aB[p].w += f.w;
            aA[p].x = fmaf(f.x, sA, aA[p].x);
            aA[p].y = fmaf(f.y, sA, aA[p].y);
            aA[p].z = fmaf(f.z, sA, aA[p].z);
            aA[p].w = fmaf(f.w, sA, aA[p].w);
        }
    }
#pragma unroll
    for (int p = 0; p < PNUM; p++) {
        ((uint2*)g_embA[p])[rr * 16 + l] = pack_half4(aA[p]);
        ((uint2*)g_embB[p])[rr * 16 + l] = pack_half4(aB[p]);
    }
}

__global__ __launch_bounds__(256) void spmm_mask_all(const float* __restrict__ b, int n)
{
    if (blockIdx.x == 0 && threadIdx.x < PNUM * HDIM)
        g_s[0][threadIdx.x] = 0.f;

    int rr = blockIdx.x * 16 + (threadIdx.x >> 4);
    int l = threadIdx.x & 15;
    if (rr >= n) return;
    int beg = g_off[rr], end = g_off[rr + 1];

    float4 aA[PNUM];
#pragma unroll
    for (int p = 0; p < PNUM; p++)
        aA[p] = __ldg(((const float4*)(b + p * HDIM)) + l);

#pragma unroll 4
    for (int i = beg; i < end; i++) {
        int2 ed = __ldcs(g_edge + i);
        float v = (ed.x & (1u << 31)) ? 0.f : __int_as_float(ed.y);
        int c = ed.x & 0xFFFFFF;
#pragma unroll
        for (int p = 0; p < PNUM; p++) {
            uint2 u = __ldg(((const uint2*)g_fts16[p]) + c * 16 + l);
            float4 f = gath_mul(u, v);
            aA[p].x += f.x; aA[p].y += f.y; aA[p].z += f.z; aA[p].w += f.w;
        }
    }
#pragma unroll
    for (int p = 0; p < PNUM; p++)
        ((uint2*)g_embA[p])[rr * 16 + l] = pack_half4(aA[p]);
}

// ===========================================================================
// combine: inline softmax(beta) from g_s, then weighted prelu-combine
// ===========================================================================
__global__ void combine_k(int sel, int writez, const float* __restrict__ a,
                          const float* __restrict__ att, float* __restrict__ out, int n)
{
    __shared__ float sbeta[PNUM];
    int t = threadIdx.x;
    {
        int w = t >> 5, l = t & 31;
        if (w < PNUM) {
            float v = g_s[sel][w * 64 + l] * __ldg(att + l)
                    + g_s[sel][w * 64 + 32 + l] * __ldg(att + 32 + l);
#pragma unroll
            for (int o = 16; o; o >>= 1) v += __shfl_down_sync(0xffffffffu, v, o);
            if (l == 0) sbeta[w] = v / (float)n;
        }
    }
    __syncthreads();
    if (t == 0) {
        float m = fmaxf(sbeta[0], fmaxf(sbeta[1], sbeta[2]));
        float e0 = expf(sbeta[0] - m), e1 = expf(sbeta[1] - m), e2 = expf(sbeta[2] - m);
        float inv = 1.f / (e0 + e1 + e2);
        sbeta[0] = e0 * inv; sbeta[1] = e1 * inv; sbeta[2] = e2 * inv;
    }
    __syncthreads();

    int idx = blockIdx.x * blockDim.x + t;
    if (idx >= n * 16) return;
    float b0 = sbeta[0], b1 = sbeta[1], b2 = sbeta[2];
    float s0 = __ldg(a), s1 = __ldg(a + 1), s2 = __ldg(a + 2);
    const uint2* E0 = (const uint2*)(sel == 0 ? g_embA[0] : g_embB[0]);
    const uint2* E1 = (const uint2*)(sel == 0 ? g_embA[1] : g_embB[1]);
    const uint2* E2 = (const uint2*)(sel == 0 ? g_embA[2] : g_embB[2]);
    float4 e0 = gath_mul(E0[idx], 1.f);
    float4 e1 = gath_mul(E1[idx], 1.f);
    float4 e2 = gath_mul(E2[idx], 1.f);
    float4 o;
    o.x = b0 * prelu_f(e0.x, s0) + b1 * prelu_f(e1.x, s1) + b2 * prelu_f(e2.x, s2);
    o.y = b0 * prelu_f(e0.y, s0) + b1 * prelu_f(e1.y, s1) + b2 * prelu_f(e2.y, s2);
    o.z = b0 * prelu_f(e0.z, s0) + b1 * prelu_f(e1.z, s1) + b2 * prelu_f(e2.z, s2);
    o.w = b0 * prelu_f(e0.w, s0) + b1 * prelu_f(e1.w, s1) + b2 * prelu_f(e2.w, s2);
    ((float4*)out)[idx] = o;
    if (writez) ((uint2*)g_z16)[idx] = pack_half4(o);
}

// ===========================================================================
extern "C" void kernel_launch(void* const* d_in, const int* in_sizes, int n_in,
                              void* d_out, int out_size)
{
    const float* h     = (const float*)d_in[0];
    const float* W     = (const float*)d_in[1];
    const float* b     = (const float*)d_in[2];
    const float* a     = (const float*)d_in[3];
    const float* fcw   = (const float*)d_in[4];
    const float* fcb   = (const float*)d_in[5];
    const float* att   = (const float*)d_in[6];
    const float* adj   = (const float*)d_in[7];
    const int*   row   = (const int*)d_in[8];
    const int*   col   = (const int*)d_in[9];
    const int*   mask1 = (const int*)d_in[10];
    const int*   mask2 = (const int*)d_in[11];

    int n = in_sizes[0] / HDIM;
    int e = in_sizes[7];

    float* out   = (float*)d_out;
    float* z_mp  = out;
    float* z_mp2 = out + (size_t)n * HDIM;
    float* x_rec = out + (size_t)2 * n * HDIM;

    int gGemm = (n + 127) / 128;
    int gEW   = (n * 16 + 255) / 256;
    int gSp   = (n + 15) / 16;
    int gE    = (e + 255) / 256;
    int gN    = (n + 255) / 256;

    static cudaStream_t s2 = nullptr;
    static cudaEvent_t evFork = nullptr, evCsr = nullptr, evSpmm = nullptr, evDone = nullptr;
    if (s2 == nullptr) {
        cudaStreamCreateWithFlags(&s2, cudaStreamNonBlocking);
        cudaEventCreateWithFlags(&evFork, cudaEventDisableTiming);
        cudaEventCreateWithFlags(&evCsr, cudaEventDisableTiming);
        cudaEventCreateWithFlags(&evSpmm, cudaEventDisableTiming);
        cudaEventCreateWithFlags(&evDone, cudaEventDisableTiming);
    }
    cudaStream_t s0 = 0;

    // ---- fork: CSR build on s2, pass-1 GEMM on main (independent) ----
    cudaEventRecord(evFork, s0);
    cudaStreamWaitEvent(s2, evFork, 0);

    csr_zero<<<gN, 256, 0, s2>>>(n);
    csr_hist<<<gE, 256, 0, s2>>>(row, e);
    csr_scan<<<1, 1024, 0, s2>>>(n);
    csr_scatter<<<gE, 256, 0, s2>>>(row, col, adj, mask1, mask2, e);
    cudaEventRecord(evCsr, s2);

    gemm_gcn_mma<<<gGemm, 128, 0, s0>>>(h, W, n);

    // ---- join: SpMM needs CSR + fts (also zeroes g_s[0..1]) ----
    cudaStreamWaitEvent(s0, evCsr, 0);
    spmm_dual_all<<<gSp, 256, 0, s0>>>(b, n);
    cudaEventRecord(evSpmm, s0);

    // ---- branch B on s2: sel=1 chain (z_mp2), independent of pass 3 ----
    cudaStreamWaitEvent(s2, evSpmm, 0);
    att_gemm_mma<<<dim3(gGemm, PNUM), 128, 0, s2>>>(1, a, fcw, fcb, n);
    combine_k<<<gEW, 256, 0, s2>>>(1, 0, a, att, z_mp2, n);
    cudaEventRecord(evDone, s2);

    // ---- main chain: sel=0 then pass 3 ----
    att_gemm_mma<<<dim3(gGemm, PNUM), 128, 0, s0>>>(0, a, fcw, fcb, n);
    combine_k<<<gEW, 256, 0, s0>>>(0, 1, a, att, z_mp, n);   // also writes g_z16

    gemm_gcn_mma_h<<<gGemm, 128, 0, s0>>>(W, n);
    spmm_mask_all<<<gSp, 256, 0, s0>>>(b, n);                // zeroes g_s[0]
    att_gemm_mma<<<dim3(gGemm, PNUM), 128, 0, s0>>>(0, a, fcw, fcb, n);
    combine_k<<<gEW, 256, 0, s0>>>(0, 0, a, att, x_rec, n);

    // ---- final join ----
    cudaStreamWaitEvent(s0, evDone, 0);
}

// round 17
// speedup vs baseline: 1.0608x; 1.0243x over previous
#include <cuda_runtime.h>
#include <cuda_fp16.h>
#include <stdint.h>
#include <math.h>

// Problem constants: N=100000, H=64, E=1600000, P=3
#define NMAX 100000
#define EMAX 1600000
#define HDIM 64
#define PNUM 3

// ---------------- scratch (no allocation allowed -> device globals) -------
__device__ __align__(16) __half g_fts16[PNUM][NMAX * HDIM];   // 38.4 MB
__device__ __align__(16) __half g_embA[PNUM][NMAX * HDIM];    // 19.2 MB
__device__ __align__(16) __half g_embB[PNUM][NMAX * HDIM];    // 19.2 MB
__device__ __align__(16) __half g_z16[NMAX * HDIM];           // 12.8 MB (z_mp fp16)
__device__ float g_s[2][PNUM * HDIM];

// CSR scratch
__device__ int  g_deg[NMAX];
__device__ int  g_off[NMAX + 1];
__device__ int  g_cur[NMAX];
__device__ __align__(16) int2 g_edge[EMAX];   // .x = col | m1<<30 | m2<<31, .y = val bits

__device__ __forceinline__ float prelu_f(float x, float s) { return x > 0.f ? x : s * x; }

__device__ __forceinline__ uint32_t h2_bits(__half2 h)
{
    return *reinterpret_cast<uint32_t*>(&h);
}

// m16n8k16 row.col HMMA, fp16 inputs, fp32 accumulate
__device__ __forceinline__ void mma_16816(float* c, const uint32_t* a, const uint32_t* b)
{
    asm volatile("mma.sync.aligned.m16n8k16.row.col.f32.f16.f16.f32 "
                 "{%0,%1,%2,%3}, {%4,%5,%6,%7}, {%8,%9}, {%0,%1,%2,%3};"
                 : "+f"(c[0]), "+f"(c[1]), "+f"(c[2]), "+f"(c[3])
                 : "r"(a[0]), "r"(a[1]), "r"(a[2]), "r"(a[3]), "r"(b[0]), "r"(b[1]));
}

#define APAD 72   // padded half-stride: conflict-free 4B fragment loads

__device__ __forceinline__ float4 gath_mul(uint2 u, float v)
{
    float2 f01 = __half22float2(*(const __half2*)&u.x);
    float2 f23 = __half22float2(*(const __half2*)&u.y);
    return make_float4(f01.x * v, f01.y * v, f23.x * v, f23.y * v);
}
__device__ __forceinline__ uint2 pack_half4(float4 a)
{
    __half2 h0 = __floats2half2_rn(a.x, a.y);
    __half2 h1 = __floats2half2_rn(a.z, a.w);
    return make_uint2(h2_bits(h0), h2_bits(h1));
}

// ===========================================================================
// CSR build
// ===========================================================================
__global__ void csr_zero(int n)
{
    int i = blockIdx.x * blockDim.x + threadIdx.x;
    if (i < n) g_deg[i] = 0;
}
__global__ void csr_hist(const int* __restrict__ row, int e)
{
    int i = blockIdx.x * blockDim.x + threadIdx.x;
    if (i < e) atomicAdd(&g_deg[row[i]], 1);
}
__global__ void csr_scan(int n)
{
    __shared__ int part[1024];
    int tid = threadIdx.x;
    int chunk = (n + 1023) >> 10;
    int beg = tid * chunk;
    int end = min(beg + chunk, n);
    int s = 0;
    for (int i = beg; i < end; i++) s += g_deg[i];
    part[tid] = s;
    __syncthreads();
    for (int o = 1; o < 1024; o <<= 1) {
        int t2 = (tid >= o) ? part[tid - o] : 0;
        __syncthreads();
        part[tid] += t2;
        __syncthreads();
    }
    int run = part[tid] - s;
    for (int i = beg; i < end; i++) {
        g_off[i] = run; g_cur[i] = run;
        run += g_deg[i];
    }
    if (tid == 1023) g_off[n] = part[1023];
}
__global__ void csr_scatter(const int* __restrict__ row, const int* __restrict__ col,
                            const float* __restrict__ vals,
                            const int* __restrict__ mask1, const int* __restrict__ mask2,
                            int e)
{
    int i = blockIdx.x * blockDim.x + threadIdx.x;
    if (i >= e) return;
    int r = __ldg(row + i), c = __ldg(col + i);
    float v = __ldg(vals + i);
    int fl = c | (__ldg(mask1 + c) ? (1 << 30) : 0) | (__ldg(mask2 + c) ? (1u << 31) : 0);
    int pos = atomicAdd(&g_cur[r], 1);
    g_edge[pos] = make_int2(fl, __float_as_int(v));
}

// ===========================================================================
// GCN GEMM via HMMA (fp32 input): loop p per 128-row tile
// ===========================================================================
__global__ __launch_bounds__(128) void gemm_gcn_mma(
    const float* __restrict__ X, const float* __restrict__ Wall, int n)
{
    __shared__ __half smA[128 * APAD];
    __shared__ __half smB[64 * APAD];

    int t = threadIdx.x, wid = t >> 5, lane = t & 31;
    int g = lane >> 2, q = lane & 3;
    int rowBase = blockIdx.x * 128;

#pragma unroll
    for (int i = 0; i < 16; i++) {
        int idx = t + i * 128;
        int r = idx >> 4, k4 = idx & 15;
        int gr = rowBase + r;
        float4 v = make_float4(0.f, 0.f, 0.f, 0.f);
        if (gr < n) v = __ldg(((const float4*)X) + gr * 16 + k4);
        __half* dst = &smA[r * APAD + k4 * 4];
        *(__half2*)(dst)     = __floats2half2_rn(v.x, v.y);
        *(__half2*)(dst + 2) = __floats2half2_rn(v.z, v.w);
    }

    for (int p = 0; p < PNUM; p++) {
        __syncthreads();
#pragma unroll
        for (int i = 0; i < 8; i++) {
            int idx = t + i * 128;
            int r = idx >> 4, k4 = idx & 15;
            float4 v = __ldg(((const float4*)(Wall + p * 4096)) + r * 16 + k4);
            __half* dst = &smB[r * APAD + k4 * 4];
            *(__half2*)(dst)     = __floats2half2_rn(v.x, v.y);
            *(__half2*)(dst + 2) = __floats2half2_rn(v.z, v.w);
        }
        __syncthreads();

        float acc[2][8][4];
#pragma unroll
        for (int mt = 0; mt < 2; mt++)
#pragma unroll
            for (int nt = 0; nt < 8; nt++)
#pragma unroll
                for (int c = 0; c < 4; c++) acc[mt][nt][c] = 0.f;

#pragma unroll
        for (int ks = 0; ks < 4; ks++) {
            uint32_t afr[2][4];
#pragma unroll
            for (int mt = 0; mt < 2; mt++) {
                int r0 = wid * 32 + mt * 16 + g;
                int kb = ks * 16 + q * 2;
                afr[mt][0] = *(const uint32_t*)&smA[r0 * APAD + kb];
                afr[mt][1] = *(const uint32_t*)&smA[(r0 + 8) * APAD + kb];
                afr[mt][2] = *(const uint32_t*)&smA[r0 * APAD + kb + 8];
                afr[mt][3] = *(const uint32_t*)&smA[(r0 + 8) * APAD + kb + 8];
            }
#pragma unroll
            for (int nt = 0; nt < 8; nt++) {
                int cb = (nt * 8 + g) * APAD + ks * 16 + q * 2;
                uint32_t bfr[2];
                bfr[0] = *(const uint32_t*)&smB[cb];
                bfr[1] = *(const uint32_t*)&smB[cb + 8];
                mma_16816(acc[0][nt], afr[0], bfr);
                mma_16816(acc[1][nt], afr[1], bfr);
            }
        }

        __half* F = g_fts16[p];
#pragma unroll
        for (int mt = 0; mt < 2; mt++) {
            int r0 = rowBase + wid * 32 + mt * 16 + g;
#pragma unroll
            for (int nt = 0; nt < 8; nt++) {
                int col = nt * 8 + q * 2;
                if (r0 < n)
                    *(__half2*)(F + (size_t)r0 * 64 + col) =
                        __floats2half2_rn(acc[mt][nt][0], acc[mt][nt][1]);
                if (r0 + 8 < n)
                    *(__half2*)(F + (size_t)(r0 + 8) * 64 + col) =
                        __floats2half2_rn(acc[mt][nt][2], acc[mt][nt][3]);
            }
        }
    }
}

// fp16-input variant (pass 3: reads g_z16 directly)
__global__ __launch_bounds__(128) void gemm_gcn_mma_h(
    const float* __restrict__ Wall, int n)
{
    __shared__ __half smA[128 * APAD];
    __shared__ __half smB[64 * APAD];

    int t = threadIdx.x, wid = t >> 5, lane = t & 31;
    int g = lane >> 2, q = lane & 3;
    int rowBase = blockIdx.x * 128;

#pragma unroll
    for (int i = 0; i < 16; i++) {
        int idx = t + i * 128;
        int r = idx >> 4, k4 = idx & 15;
        int gr = rowBase + r;
        uint2 u = make_uint2(0u, 0u);
        if (gr < n) u = *((const uint2*)(g_z16 + (size_t)gr * 64 + k4 * 4));
        *(uint2*)&smA[r * APAD + k4 * 4] = u;
    }

    for (int p = 0; p < PNUM; p++) {
        __syncthreads();
#pragma unroll
        for (int i = 0; i < 8; i++) {
            int idx = t + i * 128;
            int r = idx >> 4, k4 = idx & 15;
            float4 v = __ldg(((const float4*)(Wall + p * 4096)) + r * 16 + k4);
            __half* dst = &smB[r * APAD + k4 * 4];
            *(__half2*)(dst)     = __floats2half2_rn(v.x, v.y);
            *(__half2*)(dst + 2) = __floats2half2_rn(v.z, v.w);
        }
        __syncthreads();

        float acc[2][8][4];
#pragma unroll
        for (int mt = 0; mt < 2; mt++)
#pragma unroll
            for (int nt = 0; nt < 8; nt++)
#pragma unroll
                for (int c = 0; c < 4; c++) acc[mt][nt][c] = 0.f;

#pragma unroll
        for (int ks = 0; ks < 4; ks++) {
            uint32_t afr[2][4];
#pragma unroll
            for (int mt = 0; mt < 2; mt++) {
                int r0 = wid * 32 + mt * 16 + g;
                int kb = ks * 16 + q * 2;
                afr[mt][0] = *(const uint32_t*)&smA[r0 * APAD + kb];
                afr[mt][1] = *(const uint32_t*)&smA[(r0 + 8) * APAD + kb];
                afr[mt][2] = *(const uint32_t*)&smA[r0 * APAD + kb + 8];
                afr[mt][3] = *(const uint32_t*)&smA[(r0 + 8) * APAD + kb + 8];
            }
#pragma unroll
            for (int nt = 0; nt < 8; nt++) {
                int cb = (nt * 8 + g) * APAD + ks * 16 + q * 2;
                uint32_t bfr[2];
                bfr[0] = *(const uint32_t*)&smB[cb];
                bfr[1] = *(const uint32_t*)&smB[cb + 8];
                mma_16816(acc[0][nt], afr[0], bfr);
                mma_16816(acc[1][nt], afr[1], bfr);
            }
        }

        __half* F = g_fts16[p];
#pragma unroll
        for (int mt = 0; mt < 2; mt++) {
            int r0 = rowBase + wid * 32 + mt * 16 + g;
#pragma unroll
            for (int nt = 0; nt < 8; nt++) {
                int col = nt * 8 + q * 2;
                if (r0 < n)
                    *(__half2*)(F + (size_t)r0 * 64 + col) =
                        __floats2half2_rn(acc[mt][nt][0], acc[mt][nt][1]);
                if (r0 + 8 < n)
                    *(__half2*)(F + (size_t)(r0 + 8) * 64 + col) =
                        __floats2half2_rn(acc[mt][nt][2], acc[mt][nt][3]);
            }
        }
    }
}

// ===========================================================================
// Attention GEMM via HMMA (fp16 emb input): grid = (tiles, p), sel as arg
// ===========================================================================
__global__ __launch_bounds__(128) void att_gemm_mma(
    int sel, const float* __restrict__ a,
    const float* __restrict__ fcw, const float* __restrict__ fcb, int n)
{
    __shared__ __half smA[128 * APAD];
    __shared__ __half smB[64 * APAD];
    __shared__ float ssum[64];

    int t = threadIdx.x, wid = t >> 5, lane = t & 31;
    int g = lane >> 2, q = lane & 3;
    int rowBase = blockIdx.x * 128;
    int p = blockIdx.y;
    float sa = __ldg(a + p);
    const __half* E = (sel == 0) ? g_embA[p] : g_embB[p];

    if (t < 64) ssum[t] = 0.f;

#pragma unroll
    for (int i = 0; i < 16; i++) {
        int idx = t + i * 128;
        int r = idx >> 4, k4 = idx & 15;
        int gr = rowBase + r;
        float4 v = make_float4(0.f, 0.f, 0.f, 0.f);
        if (gr < n) {
            uint2 u = *((const uint2*)(E + (size_t)gr * 64 + k4 * 4));
            float2 f01 = __half22float2(*(__half2*)&u.x);
            float2 f23 = __half22float2(*(__half2*)&u.y);
            v.x = prelu_f(f01.x, sa); v.y = prelu_f(f01.y, sa);
            v.z = prelu_f(f23.x, sa); v.w = prelu_f(f23.y, sa);
        }
        __half* dst = &smA[r * APAD + k4 * 4];
        *(__half2*)(dst)     = __floats2half2_rn(v.x, v.y);
        *(__half2*)(dst + 2) = __floats2half2_rn(v.z, v.w);
    }
#pragma unroll
    for (int i = 0; i < 8; i++) {
        int idx = t + i * 128;
        int r = idx >> 4, k4 = idx & 15;
        float4 v = __ldg(((const float4*)fcw) + r * 16 + k4);
        __half* dst = &smB[r * APAD + k4 * 4];
        *(__half2*)(dst)     = __floats2half2_rn(v.x, v.y);
        *(__half2*)(dst + 2) = __floats2half2_rn(v.z, v.w);
    }
    __syncthreads();

    float acc[2][8][4];
#pragma unroll
    for (int mt = 0; mt < 2; mt++)
#pragma unroll
        for (int nt = 0; nt < 8; nt++)
#pragma unroll
            for (int c = 0; c < 4; c++) acc[mt][nt][c] = 0.f;

#pragma unroll
    for (int ks = 0; ks < 4; ks++) {
        uint32_t afr[2][4];
#pragma unroll
        for (int mt = 0; mt < 2; mt++) {
            int r0 = wid * 32 + mt * 16 + g;
            int kb = ks * 16 + q * 2;
            afr[mt][0] = *(const uint32_t*)&smA[r0 * APAD + kb];
            afr[mt][1] = *(const uint32_t*)&smA[(r0 + 8) * APAD + kb];
            afr[mt][2] = *(const uint32_t*)&smA[r0 * APAD + kb + 8];
            afr[mt][3] = *(const uint32_t*)&smA[(r0 + 8) * APAD + kb + 8];
        }
#pragma unroll
        for (int nt = 0; nt < 8; nt++) {
            int cb = (nt * 8 + g) * APAD + ks * 16 + q * 2;
            uint32_t bfr[2];
            bfr[0] = *(const uint32_t*)&smB[cb];
            bfr[1] = *(const uint32_t*)&smB[cb + 8];
            mma_16816(acc[0][nt], afr[0], bfr);
            mma_16816(acc[1][nt], afr[1], bfr);
        }
    }

    float colsum[16];
#pragma unroll
    for (int i = 0; i < 16; i++) colsum[i] = 0.f;
#pragma unroll
    for (int mt = 0; mt < 2; mt++) {
        int r0 = rowBase + wid * 32 + mt * 16 + g;
#pragma unroll
        for (int nt = 0; nt < 8; nt++) {
            int col = nt * 8 + q * 2;
            float fb0 = __ldg(fcb + col), fb1 = __ldg(fcb + col + 1);
            if (r0 < n) {
                colsum[nt * 2]     += tanhf(acc[mt][nt][0] + fb0);
                colsum[nt * 2 + 1] += tanhf(acc[mt][nt][1] + fb1);
            }
            if (r0 + 8 < n) {
                colsum[nt * 2]     += tanhf(acc[mt][nt][2] + fb0);
                colsum[nt * 2 + 1] += tanhf(acc[mt][nt][3] + fb1);
            }
        }
    }
#pragma unroll
    for (int o = 4; o < 32; o <<= 1) {
#pragma unroll
        for (int i = 0; i < 16; i++)
            colsum[i] += __shfl_xor_sync(0xffffffffu, colsum[i], o);
    }
    if (lane < 4) {
#pragma unroll
        for (int nt = 0; nt < 8; nt++) {
            atomicAdd(&ssum[nt * 8 + q * 2], colsum[nt * 2]);
            atomicAdd(&ssum[nt * 8 + q * 2 + 1], colsum[nt * 2 + 1]);
        }
    }
    __syncthreads();
    if (t < 64) atomicAdd(&g_s[sel][p * 64 + t], ssum[t]);
}

// ===========================================================================
// CSR SpMM: 4-edge batching, branchless masking, fp16 in/out, fp32 accumulate
// ===========================================================================
__global__ __launch_bounds__(256) void spmm_dual_all(const float* __restrict__ b, int n)
{
    if (blockIdx.x == 0 && threadIdx.x < PNUM * HDIM) {
        g_s[0][threadIdx.x] = 0.f;
        g_s[1][threadIdx.x] = 0.f;
    }

    int rr = blockIdx.x * 16 + (threadIdx.x >> 4);
    int l = threadIdx.x & 15;
    if (rr >= n) return;
    int beg = g_off[rr], end = g_off[rr + 1];

    float4 aA[PNUM], aB[PNUM];
#pragma unroll
    for (int p = 0; p < PNUM; p++) {
        float4 bias = __ldg(((const float4*)(b + p * HDIM)) + l);
        aA[p] = bias; aB[p] = bias;
    }

    int i = beg;
#pragma unroll 1
    for (; i + 4 <= end; i += 4) {
        int2 ed[4];
#pragma unroll
        for (int j = 0; j < 4; j++) ed[j] = __ldg(g_edge + i + j);
        uint2 u[4][PNUM];
#pragma unroll
        for (int j = 0; j < 4; j++) {
            int c = ed[j].x & 0xFFFFFF;
#pragma unroll
            for (int p = 0; p < PNUM; p++)
                u[j][p] = __ldg(((const uint2*)g_fts16[p]) + c * 16 + l);
        }
#pragma unroll
        for (int j = 0; j < 4; j++) {
            float v = __int_as_float(ed[j].y);
            float sA = (ed[j].x & (1 << 30)) ? 0.f : 1.f;
#pragma unroll
            for (int p = 0; p < PNUM; p++) {
                float4 f = gath_mul(u[j][p], v);
                aB[p].x += f.x; aB[p].y += f.y; aB[p].z += f.z; aB[p].w += f.w;
                aA[p].x = fmaf(f.x, sA, aA[p].x);
                aA[p].y = fmaf(f.y, sA, aA[p].y);
                aA[p].z = fmaf(f.z, sA, aA[p].z);
                aA[p].w = fmaf(f.w, sA, aA[p].w);
            }
        }
    }
#pragma unroll 1
    for (; i < end; i++) {
        int2 ed = __ldg(g_edge + i);
        int c = ed.x & 0xFFFFFF;
        float v = __int_as_float(ed.y);
        float sA = (ed.x & (1 << 30)) ? 0.f : 1.f;
#pragma unroll
        for (int p = 0; p < PNUM; p++) {
            uint2 u = __ldg(((const uint2*)g_fts16[p]) + c * 16 + l);
            float4 f = gath_mul(u, v);
            aB[p].x += f.x; aB[p].y += f.y; aB[p].z += f.z; aB[p].w += f.w;
            aA[p].x = fmaf(f.x, sA, aA[p].x);
            aA[p].y = fmaf(f.y, sA, aA[p].y);
            aA[p].z = fmaf(f.z, sA, aA[p].z);
            aA[p].w = fmaf(f.w, sA, aA[p].w);
        }
    }
#pragma unroll
    for (int p = 0; p < PNUM; p++) {
        ((uint2*)g_embA[p])[rr * 16 + l] = pack_half4(aA[p]);
        ((uint2*)g_embB[p])[rr * 16 + l] = pack_half4(aB[p]);
    }
}

__global__ __launch_bounds__(256) void spmm_mask_all(const float* __restrict__ b, int n)
{
    if (blockIdx.x == 0 && threadIdx.x < PNUM * HDIM)
        g_s[0][threadIdx.x] = 0.f;

    int rr = blockIdx.x * 16 + (threadIdx.x >> 4);
    int l = threadIdx.x & 15;
    if (rr >= n) return;
    int beg = g_off[rr], end = g_off[rr + 1];

    float4 aA[PNUM];
#pragma unroll
    for (int p = 0; p < PNUM; p++)
        aA[p] = __ldg(((const float4*)(b + p * HDIM)) + l);

    int i = beg;
#pragma unroll 1
    for (; i + 4 <= end; i += 4) {
        int2 ed[4];
#pragma unroll
        for (int j = 0; j < 4; j++) ed[j] = __ldg(g_edge + i + j);
        uint2 u[4][PNUM];
#pragma unroll
        for (int j = 0; j < 4; j++) {
            int c = ed[j].x & 0xFFFFFF;
#pragma unroll
            for (int p = 0; p < PNUM; p++)
                u[j][p] = __ldg(((const uint2*)g_fts16[p]) + c * 16 + l);
        }
#pragma unroll
        for (int j = 0; j < 4; j++) {
            float v = (ed[j].x & (1u << 31)) ? 0.f : __int_as_float(ed[j].y);
#pragma unroll
            for (int p = 0; p < PNUM; p++) {
                float4 f = gath_mul(u[j][p], v);
                aA[p].x += f.x; aA[p].y += f.y; aA[p].z += f.z; aA[p].w += f.w;
            }
        }
    }
#pragma unroll 1
    for (; i < end; i++) {
        int2 ed = __ldg(g_edge + i);
        int c = ed.x & 0xFFFFFF;
        float v = (ed.x & (1u << 31)) ? 0.f : __int_as_float(ed.y);
#pragma unroll
        for (int p = 0; p < PNUM; p++) {
            uint2 u = __ldg(((const uint2*)g_fts16[p]) + c * 16 + l);
            float4 f = gath_mul(u, v);
            aA[p].x += f.x; aA[p].y += f.y; aA[p].z += f.z; aA[p].w += f.w;
        }
    }
#pragma unroll
    for (int p = 0; p < PNUM; p++)
        ((uint2*)g_embA[p])[rr * 16 + l] = pack_half4(aA[p]);
}

// ===========================================================================
// combine: inline softmax(beta) from g_s, then weighted prelu-combine
// ===========================================================================
__global__ void combine_k(int sel, int writez, const float* __restrict__ a,
                          const float* __restrict__ att, float* __restrict__ out, int n)
{
    __shared__ float sbeta[PNUM];
    int t = threadIdx.x;
    {
        int w = t >> 5, l = t & 31;
        if (w < PNUM) {
            float v = g_s[sel][w * 64 + l] * __ldg(att + l)
                    + g_s[sel][w * 64 + 32 + l] * __ldg(att + 32 + l);
#pragma unroll
            for (int o = 16; o; o >>= 1) v += __shfl_down_sync(0xffffffffu, v, o);
            if (l == 0) sbeta[w] = v / (float)n;
        }
    }
    __syncthreads();
    if (t == 0) {
        float m = fmaxf(sbeta[0], fmaxf(sbeta[1], sbeta[2]));
        float e0 = expf(sbeta[0] - m), e1 = expf(sbeta[1] - m), e2 = expf(sbeta[2] - m);
        float inv = 1.f / (e0 + e1 + e2);
        sbeta[0] = e0 * inv; sbeta[1] = e1 * inv; sbeta[2] = e2 * inv;
    }
    __syncthreads();

    int idx = blockIdx.x * blockDim.x + t;
    if (idx >= n * 16) return;
    float b0 = sbeta[0], b1 = sbeta[1], b2 = sbeta[2];
    float s0 = __ldg(a), s1 = __ldg(a + 1), s2 = __ldg(a + 2);
    const uint2* E0 = (const uint2*)(sel == 0 ? g_embA[0] : g_embB[0]);
    const uint2* E1 = (const uint2*)(sel == 0 ? g_embA[1] : g_embB[1]);
    const uint2* E2 = (const uint2*)(sel == 0 ? g_embA[2] : g_embB[2]);
    float4 e0 = gath_mul(E0[idx], 1.f);
    float4 e1 = gath_mul(E1[idx], 1.f);
    float4 e2 = gath_mul(E2[idx], 1.f);
    float4 o;
    o.x = b0 * prelu_f(e0.x, s0) + b1 * prelu_f(e1.x, s1) + b2 * prelu_f(e2.x, s2);
    o.y = b0 * prelu_f(e0.y, s0) + b1 * prelu_f(e1.y, s1) + b2 * prelu_f(e2.y, s2);
    o.z = b0 * prelu_f(e0.z, s0) + b1 * prelu_f(e1.z, s1) + b2 * prelu_f(e2.z, s2);
    o.w = b0 * prelu_f(e0.w, s0) + b1 * prelu_f(e1.w, s1) + b2 * prelu_f(e2.w, s2);
    ((float4*)out)[idx] = o;
    if (writez) ((uint2*)g_z16)[idx] = pack_half4(o);
}

// ===========================================================================
extern "C" void kernel_launch(void* const* d_in, const int* in_sizes, int n_in,
                              void* d_out, int out_size)
{
    const float* h     = (const float*)d_in[0];
    const float* W     = (const float*)d_in[1];
    const float* b     = (const float*)d_in[2];
    const float* a     = (const float*)d_in[3];
    const float* fcw   = (const float*)d_in[4];
    const float* fcb   = (const float*)d_in[5];
    const float* att   = (const float*)d_in[6];
    const float* adj   = (const float*)d_in[7];
    const int*   row   = (const int*)d_in[8];
    const int*   col   = (const int*)d_in[9];
    const int*   mask1 = (const int*)d_in[10];
    const int*   mask2 = (const int*)d_in[11];

    int n = in_sizes[0] / HDIM;
    int e = in_sizes[7];

    float* out   = (float*)d_out;
    float* z_mp  = out;
    float* z_mp2 = out + (size_t)n * HDIM;
    float* x_rec = out + (size_t)2 * n * HDIM;

    int gGemm = (n + 127) / 128;
    int gEW   = (n * 16 + 255) / 256;
    int gSp   = (n + 15) / 16;
    int gE    = (e + 255) / 256;
    int gN    = (n + 255) / 256;

    static cudaStream_t s2 = nullptr;
    static cudaEvent_t evFork = nullptr, evCsr = nullptr, evSpmm = nullptr, evDone = nullptr;
    if (s2 == nullptr) {
        cudaStreamCreateWithFlags(&s2, cudaStreamNonBlocking);
        cudaEventCreateWithFlags(&evFork, cudaEventDisableTiming);
        cudaEventCreateWithFlags(&evCsr, cudaEventDisableTiming);
        cudaEventCreateWithFlags(&evSpmm, cudaEventDisableTiming);
        cudaEventCreateWithFlags(&evDone, cudaEventDisableTiming);
        // prefer-L1 carveout on the gather-bound SpMM kernels (they use 0 smem)
        cudaFuncSetAttribute(spmm_dual_all,
                             cudaFuncAttributePreferredSharedMemoryCarveout, 0);
        cudaFuncSetAttribute(spmm_mask_all,
                             cudaFuncAttributePreferredSharedMemoryCarveout, 0);
    }
    cudaStream_t s0 = 0;

    // ---- fork: CSR build on s2, pass-1 GEMM on main (independent) ----
    cudaEventRecord(evFork, s0);
    cudaStreamWaitEvent(s2, evFork, 0);

    csr_zero<<<gN, 256, 0, s2>>>(n);
    csr_hist<<<gE, 256, 0, s2>>>(row, e);
    csr_scan<<<1, 1024, 0, s2>>>(n);
    csr_scatter<<<gE, 256, 0, s2>>>(row, col, adj, mask1, mask2, e);
    cudaEventRecord(evCsr, s2);

    gemm_gcn_mma<<<gGemm, 128, 0, s0>>>(h, W, n);

    // ---- join: SpMM needs CSR + fts (also zeroes g_s[0..1]) ----
    cudaStreamWaitEvent(s0, evCsr, 0);
    spmm_dual_all<<<gSp, 256, 0, s0>>>(b, n);
    cudaEventRecord(evSpmm, s0);

    // ---- branch B on s2: sel=1 chain (z_mp2), independent of pass 3 ----
    cudaStreamWaitEvent(s2, evSpmm, 0);
    att_gemm_mma<<<dim3(gGemm, PNUM), 128, 0, s2>>>(1, a, fcw, fcb, n);
    combine_k<<<gEW, 256, 0, s2>>>(1, 0, a, att, z_mp2, n);
    cudaEventRecord(evDone, s2);

    // ---- main chain: sel=0 then pass 3 ----
    att_gemm_mma<<<dim3(gGemm, PNUM), 128, 0, s0>>>(0, a, fcw, fcb, n);
    combine_k<<<gEW, 256, 0, s0>>>(0, 1, a, att, z_mp, n);   // also writes g_z16

    gemm_gcn_mma_h<<<gGemm, 128, 0, s0>>>(W, n);
    spmm_mask_all<<<gSp, 256, 0, s0>>>(b, n);                // zeroes g_s[0]
    att_gemm_mma<<<dim3(gGemm, PNUM), 128, 0, s0>>>(0, a, fcw, fcb, n);
    combine_k<<<gEW, 256, 0, s0>>>(0, 0, a, att, x_rec, n);

    // ---- final join ----
    cudaStreamWaitEvent(s0, evDone, 0);
}